// round 12
// baseline (speedup 1.0000x reference)
#include <cuda_runtime.h>

#define BB 4
#define C 64
#define IC 16
#define H 128
#define W 128
#define DH 64
#define DW 64
#define NN 4096  // DH*DW

// ---------------- scratch (device globals; no allocation) ----------------
__device__ __align__(16) float g_q[BB*NN*IC];   // tf32(LOG2E*q) bits
__device__ __align__(16) float g_k[BB*IC*NN];   // transposed [b][ic][n], tf32 bits
__device__ __align__(16) float g_v[BB*NN*IC];
__device__ __align__(16) float g_y[BB*IC*NN];
__device__ __align__(16) float g_yp[2][BB*IC*NN];  // split-KV partial sums
__device__ __align__(16) float g_dp[2][BB*NN];     // split-KV partial denominators
__device__ __align__(16) unsigned long long g_wpk[C*IC];  // out_w packed pairs
__device__ __align__(16) float g_ps[2][C][1024];   // per-warp BN partials (sum, sumsq)
__device__ float g_sum[C];
__device__ float g_sqs[C];

typedef unsigned long long ull;
typedef unsigned int uint;

__device__ __forceinline__ ull pk2(float x, float y) {
    ull r;
    asm("mov.b64 %0, {%1,%2};" : "=l"(r) : "f"(x), "f"(y));
    return r;
}
__device__ __forceinline__ void upk2(ull v, float& lo, float& hi) {
    asm("mov.b64 {%0,%1}, %2;" : "=f"(lo), "=f"(hi) : "l"(v));
}
__device__ __forceinline__ void fma2(ull& d, ull a, ull b) {
    asm("fma.rn.f32x2 %0, %1, %2, %3;" : "=l"(d) : "l"(a), "l"(b), "l"(d));
}
__device__ __forceinline__ ull add2(ull a, ull b) {
    ull r;
    asm("add.rn.f32x2 %0, %1, %2;" : "=l"(r) : "l"(a), "l"(b));
    return r;
}
__device__ __forceinline__ float ex2f(float x) {
    float r;
    asm("ex2.approx.f32 %0, %1;" : "=f"(r) : "f"(x));
    return r;
}
__device__ __forceinline__ uint tf32c(float f) {
    uint r;
    asm("cvt.rna.tf32.f32 %0, %1;" : "=r"(r) : "f"(f));
    return r;
}
__device__ __forceinline__ void mma_tf32(float* c, const uint* a, uint b0, uint b1) {
    asm("mma.sync.aligned.m16n8k8.row.col.f32.tf32.tf32.f32 "
        "{%0,%1,%2,%3}, {%4,%5,%6,%7}, {%8,%9}, {%0,%1,%2,%3};"
        : "+f"(c[0]), "+f"(c[1]), "+f"(c[2]), "+f"(c[3])
        : "r"(a[0]), "r"(a[1]), "r"(a[2]), "r"(a[3]), "r"(b0), "r"(b1));
}
__device__ __forceinline__ void cpa16(uint dst, const void* src) {
    asm volatile("cp.async.ca.shared.global [%0], [%1], 16;" :: "r"(dst), "l"(src));
}

#define LOG2E 1.4426950408889634f

// ---------------- Kernel 1: downsample + Q/K/V projections (+ out_w packing) ----------------
__global__ void qkv_kernel(const float* __restrict__ x,
                           const float* __restrict__ g_w,  const float* __restrict__ g_b,
                           const float* __restrict__ th_w, const float* __restrict__ th_b,
                           const float* __restrict__ ph_w, const float* __restrict__ ph_b,
                           const float* __restrict__ out_w) {
    __shared__ float xd_s[C][32];
    __shared__ float w_s[48][C];
    __shared__ float b_s[48];
    int b = blockIdx.y, tile = blockIdx.x, tid = threadIdx.x;

    if (b == 0 && tile < 4) {
        int base = tile * 256;
        #pragma unroll
        for (int i = 0; i < 2; i++) {
            int idx = base + tid + i * 128;
            float w = out_w[idx];
            g_wpk[idx] = pk2(w, w);
        }
    }

    for (int idx = tid; idx < 48 * C; idx += 128) {
        int o = idx >> 6, c = idx & 63;
        float w;
        if (o < 16)      w = th_w[o * C + c];
        else if (o < 32) w = ph_w[(o - 16) * C + c];
        else             w = g_w[(o - 32) * C + c];
        w_s[o][c] = w;
    }
    if (tid < 48)
        b_s[tid] = (tid < 16) ? th_b[tid] : ((tid < 32) ? ph_b[tid - 16] : g_b[tid - 32]);

    int n0 = tile * 32;
    for (int idx = tid; idx < C * 32; idx += 128) {
        int c = idx >> 5, p = idx & 31;
        int n = n0 + p;
        int i = n >> 6, j = n & 63;
        xd_s[c][p] = x[(((b * C + c) * H + 2 * i + 1) * W) + 2 * j + 1];
    }
    __syncthreads();

    int p = tid & 31, og = tid >> 5;
    int n = n0 + p;
    #pragma unroll
    for (int r = 0; r < 12; r++) {
        int o = og + 4 * r;
        float a0 = b_s[o], a1 = 0.f, a2 = 0.f, a3 = 0.f;
        #pragma unroll
        for (int c = 0; c < C; c += 4) {
            a0 = fmaf(w_s[o][c + 0], xd_s[c + 0][p], a0);
            a1 = fmaf(w_s[o][c + 1], xd_s[c + 1][p], a1);
            a2 = fmaf(w_s[o][c + 2], xd_s[c + 2][p], a2);
            a3 = fmaf(w_s[o][c + 3], xd_s[c + 3][p], a3);
        }
        float acc = (a0 + a1) + (a2 + a3);
        if (o < 16)      g_q[(b * NN + n) * IC + o] = __uint_as_float(tf32c(acc * LOG2E));
        else if (o < 32) g_k[(b * IC + (o - 16)) * NN + n] = __uint_as_float(tf32c(acc));
        else             g_v[(b * NN + n) * IC + (o - 32)] = acc;
    }
}

// ---------------- Kernel 2: tensor-core flash attention, split-KV x2, 3-stage ring ----------------
#define TK 128
#define KSP 136
#define QQ 128
#define NSPLIT 2
#define KHALF (NN / NSPLIT)
#define NTILES (KHALF / TK)   // 16

struct AttnSmem {
    uint  ks[3][IC][KSP];
    __align__(16) float vs[3][TK][20];
    float redY[2][QQ][17];
    float redD[2][QQ];
};
#define ATTN_SMEM_BYTES sizeof(AttnSmem)

__global__ __launch_bounds__(512) void attn_kernel() {
    extern __shared__ __align__(16) char smem_raw[];
    AttnSmem& sm = *reinterpret_cast<AttnSmem*>(smem_raw);

    int b = blockIdx.y;
    int tile = blockIdx.x >> 1;
    int kv = blockIdx.x & 1;
    int t = threadIdx.x;
    int w = t >> 5, lane = t & 31;
    int qw = w & 7, kh = w >> 3;
    int r = lane >> 2, cc = lane & 3;
    int n0 = tile * QQ;
    int kbase = kv * KHALF;

    uint A0[4], A1[4];
    {
        const uint* qb = (const uint*)(g_q + (b * NN + n0 + qw * 16) * IC);
        A0[0] = qb[ r      * IC + cc     ];
        A0[1] = qb[(r + 8) * IC + cc     ];
        A0[2] = qb[ r      * IC + cc + 4 ];
        A0[3] = qb[(r + 8) * IC + cc + 4 ];
        A1[0] = qb[ r      * IC + cc + 8 ];
        A1[1] = qb[(r + 8) * IC + cc + 8 ];
        A1[2] = qb[ r      * IC + cc + 12];
        A1[3] = qb[(r + 8) * IC + cc + 12];
    }

    float Y0[4] = {0.f, 0.f, 0.f, 0.f};
    float Y1[4] = {0.f, 0.f, 0.f, 0.f};
    float denr = 0.f, dens = 0.f;

    const float* kb = g_k + b * IC * NN;
    const float* vb = g_v + b * NN * IC;

    int ic0s = t >> 5, col0 = t & 31;
    int vkey0 = t >> 2, vseg0 = t & 3;

    uint ks_d[3], vs_d[3];
    #pragma unroll
    for (int bf = 0; bf < 3; bf++) {
        ks_d[bf] = (uint)__cvta_generic_to_shared(&sm.ks[bf][ic0s][col0 * 4]);
        vs_d[bf] = (uint)__cvta_generic_to_shared(&sm.vs[bf][vkey0][vseg0 * 4]);
    }

    // prologue: stage tiles 0 and 1
    #pragma unroll
    for (int pt = 0; pt < 2; pt++) {
        int kt = kbase + pt * TK;
        cpa16(ks_d[pt], kb + ic0s * NN + kt + col0 * 4);
        cpa16(vs_d[pt], vb + (kt + vkey0) * IC + vseg0 * 4);
        asm volatile("cp.async.commit_group;");
    }

    for (int it = 0; it < NTILES; it++) {
        int cur = it % 3;
        // tile `it` complete for THIS thread's copies
        if (it < NTILES - 1) asm volatile("cp.async.wait_group 1;");
        else                 asm volatile("cp.async.wait_group 0;");
        // one barrier: tile `it` globally visible AND all warps done computing it-1
        __syncthreads();
        if (it + 2 < NTILES) {
            int nxt = (it + 2) % 3, kt = kbase + (it + 2) * TK;
            cpa16(ks_d[nxt], kb + ic0s * NN + kt + col0 * 4);
            cpa16(vs_d[nxt], vb + (kt + vkey0) * IC + vseg0 * 4);
            asm volatile("cp.async.commit_group;");
        }

        #pragma unroll
        for (int nt = 0; nt < 8; nt++) {
            int key0 = kh * 64 + nt * 8;
            float S[4] = {0.f, 0.f, 0.f, 0.f};
            mma_tf32(S, A0, sm.ks[cur][cc][key0 + r],     sm.ks[cur][cc + 4][key0 + r]);
            mma_tf32(S, A1, sm.ks[cur][cc + 8][key0 + r], sm.ks[cur][cc + 12][key0 + r]);

            float e0 = ex2f(S[0]);
            float e1 = ex2f(S[1]);
            float e2 = ex2f(S[2]);
            float e3 = ex2f(S[3]);
            denr += e0 + e1;
            dens += e2 + e3;

            uint P[4];
            P[0] = __float_as_uint(e0);
            P[1] = __float_as_uint(e2);
            P[2] = __float_as_uint(e1);
            P[3] = __float_as_uint(e3);
            int ka = key0 + 2 * cc;
            mma_tf32(Y0, P, __float_as_uint(sm.vs[cur][ka][r]),
                            __float_as_uint(sm.vs[cur][ka + 1][r]));
            mma_tf32(Y1, P, __float_as_uint(sm.vs[cur][ka][r + 8]),
                            __float_as_uint(sm.vs[cur][ka + 1][r + 8]));
        }
    }
    __syncthreads();   // last tile's compute done everywhere before smem reuse

    denr += __shfl_xor_sync(0xffffffffu, denr, 1);
    denr += __shfl_xor_sync(0xffffffffu, denr, 2);
    dens += __shfl_xor_sync(0xffffffffu, dens, 1);
    dens += __shfl_xor_sync(0xffffffffu, dens, 2);

    {
        int q0 = qw * 16 + r, q1 = q0 + 8;
        sm.redY[kh][q0][2 * cc]     = Y0[0];
        sm.redY[kh][q0][2 * cc + 1] = Y0[1];
        sm.redY[kh][q1][2 * cc]     = Y0[2];
        sm.redY[kh][q1][2 * cc + 1] = Y0[3];
        sm.redY[kh][q0][8 + 2 * cc]     = Y1[0];
        sm.redY[kh][q0][8 + 2 * cc + 1] = Y1[1];
        sm.redY[kh][q1][8 + 2 * cc]     = Y1[2];
        sm.redY[kh][q1][8 + 2 * cc + 1] = Y1[3];
        if (cc == 0) {
            sm.redD[kh][q0] = denr;
            sm.redD[kh][q1] = dens;
        }
    }
    __syncthreads();

    {
        int q = t >> 2, ic = (t & 3) * 4;
        #pragma unroll
        for (int j = 0; j < 4; j++) {
            float v = sm.redY[0][q][ic + j] + sm.redY[1][q][ic + j];
            g_yp[kv][(b * IC + ic + j) * NN + n0 + q] = v;
        }
        if ((t & 3) == 0)
            g_dp[kv][b * NN + n0 + q] = sm.redD[0][q] + sm.redD[1][q];
    }
}

// ---------------- Kernel 2b: merge split-KV partials, normalize ----------------
__global__ void ynorm_kernel() {
    int t = blockIdx.x * 256 + threadIdx.x;   // 0..4095
    int b = t >> 10;
    int n4 = (t & 1023) * 4;
    float4 d0 = *(const float4*)&g_dp[0][b * NN + n4];
    float4 d1 = *(const float4*)&g_dp[1][b * NN + n4];
    float4 inv;
    inv.x = 1.f / (d0.x + d1.x);
    inv.y = 1.f / (d0.y + d1.y);
    inv.z = 1.f / (d0.z + d1.z);
    inv.w = 1.f / (d0.w + d1.w);
    #pragma unroll
    for (int ic = 0; ic < IC; ic++) {
        int idx = (b * IC + ic) * NN + n4;
        float4 a = *(const float4*)&g_yp[0][idx];
        float4 c = *(const float4*)&g_yp[1][idx];
        float4 o;
        o.x = (a.x + c.x) * inv.x;
        o.y = (a.y + c.y) * inv.y;
        o.z = (a.z + c.z) * inv.z;
        o.w = (a.w + c.w) * inv.w;
        *(float4*)&g_y[idx] = o;
    }
}

// ---------------- Kernel 3: upsample + out-proj + residual + per-warp BN partials ----------------
// grid 512 (b = bx>>7, row = bx&127), block 512. Full output row per block.
__global__ __launch_bounds__(512) void fuse_kernel(const float* __restrict__ x,
                                                   const float* __restrict__ out_b,
                                                   float* __restrict__ out) {
    __shared__ __align__(8) float yup[IC][128];
    __shared__ ull wsm2[C][IC];
    __shared__ float bsm[C];
    int bx = blockIdx.x;
    int b  = bx >> 7;
    int row = bx & 127;
    int t = threadIdx.x;

    #pragma unroll
    for (int i = 0; i < 2; i++) {
        int idx = t + 512 * i;
        wsm2[idx >> 4][idx & 15] = g_wpk[idx];
    }
    if (t < C) bsm[t] = out_b[t];

    float fi = 0.5f * row - 0.5f;
    int r0 = (int)floorf(fi);
    float wi = fi - (float)r0;
    int r1 = min(r0 + 1, DH - 1);
    r0 = max(r0, 0);

    #pragma unroll
    for (int i = 0; i < 4; i++) {
        int idx = t + 512 * i;          // IC*128 = 2048 elements
        int ic = idx >> 7, p = idx & 127;
        float fj = 0.5f * p - 0.5f;
        int c0 = (int)floorf(fj);
        float wj = fj - (float)c0;
        int c1 = min(c0 + 1, DW - 1);
        c0 = max(c0, 0);
        const float* yp = g_y + (b * IC + ic) * NN;
        float v00 = yp[r0 * DW + c0], v01 = yp[r0 * DW + c1];
        float v10 = yp[r1 * DW + c0], v11 = yp[r1 * DW + c1];
        yup[ic][p] = (1.f - wi) * fmaf(wj, v01 - v00, v00)
                   +        wi  * fmaf(wj, v11 - v10, v10);
    }
    __syncthreads();

    int p2 = t & 63, cg = t >> 6;   // pixel pair 0..63, channel group 0..7 (warp-uniform)
    ull yv[16];
    #pragma unroll
    for (int i2 = 0; i2 < 16; i2++) yv[i2] = *(const ull*)&yup[i2][2 * p2];

    float s1v[8], s2v[8];
    #pragma unroll
    for (int k = 0; k < 8; k++) {
        int c = cg * 8 + k;
        float bb = bsm[c];
        ull acc = pk2(bb, bb);
        #pragma unroll
        for (int i2 = 0; i2 < 16; i2++) fma2(acc, wsm2[c][i2], yv[i2]);
        int gi = ((b * C + c) * H + row) * W + 2 * p2;
        ull xv = *(const ull*)(x + gi);
        acc = add2(acc, xv);
        *(ull*)(out + gi) = acc;
        float lo, hi;
        upk2(acc, lo, hi);
        s1v[k] = lo + hi;
        s2v[k] = fmaf(lo, lo, hi * hi);
    }

    // warp butterfly reduce; lane 0 stores per-warp partials (no atomics)
    #pragma unroll
    for (int k = 0; k < 8; k++) {
        #pragma unroll
        for (int off = 16; off; off >>= 1) {
            s1v[k] += __shfl_xor_sync(0xffffffffu, s1v[k], off);
            s2v[k] += __shfl_xor_sync(0xffffffffu, s2v[k], off);
        }
    }
    if ((t & 31) == 0) {
        int slot = bx * 2 + ((t >> 5) & 1);   // two warps per channel group
        #pragma unroll
        for (int k = 0; k < 8; k++) {
            g_ps[0][cg * 8 + k][slot] = s1v[k];
            g_ps[1][cg * 8 + k][slot] = s2v[k];
        }
    }
}

// ---------------- Kernel 3b: reduce per-warp partials (no atomics, overwrites) ----------------
__global__ void reduce_kernel() {
    __shared__ float s1s[8], s2s[8];
    int c = blockIdx.x, t = threadIdx.x;
    float s1 = 0.f, s2 = 0.f;
    #pragma unroll
    for (int i = 0; i < 4; i++) {
        s1 += g_ps[0][c][t + 256 * i];
        s2 += g_ps[1][c][t + 256 * i];
    }
    #pragma unroll
    for (int off = 16; off; off >>= 1) {
        s1 += __shfl_xor_sync(0xffffffffu, s1, off);
        s2 += __shfl_xor_sync(0xffffffffu, s2, off);
    }
    int w = t >> 5;
    if ((t & 31) == 0) { s1s[w] = s1; s2s[w] = s2; }
    __syncthreads();
    if (t == 0) {
        float a1 = 0.f, a2 = 0.f;
        #pragma unroll
        for (int i = 0; i < 8; i++) { a1 += s1s[i]; a2 += s2s[i]; }
        g_sum[c] = a1;
        g_sqs[c] = a2;
    }
}

// ---------------- Kernel 4: finalize + apply BN affine in place (8 elems/thread) ----------------
__global__ void norm_kernel(float* __restrict__ out,
                            const float* __restrict__ bn_gamma,
                            const float* __restrict__ bn_beta) {
    int e = (blockIdx.x * 256 + threadIdx.x) * 8;
    int c = (e >> 14) & 63;
    const float npix = (float)(BB * H * W);
    float mean = g_sum[c] / npix;
    float var  = g_sqs[c] / npix - mean * mean;
    float rstd = rsqrtf(var + 1e-5f);
    float a  = bn_gamma[c] * rstd;
    float sh = bn_beta[c] - mean * a;
    float4 v0 = *(float4*)(out + e);
    float4 v1 = *(float4*)(out + e + 4);
    v0.x = fmaf(v0.x, a, sh); v0.y = fmaf(v0.y, a, sh);
    v0.z = fmaf(v0.z, a, sh); v0.w = fmaf(v0.w, a, sh);
    v1.x = fmaf(v1.x, a, sh); v1.y = fmaf(v1.y, a, sh);
    v1.z = fmaf(v1.z, a, sh); v1.w = fmaf(v1.w, a, sh);
    *(float4*)(out + e)     = v0;
    *(float4*)(out + e + 4) = v1;
}

// ---------------- launch ----------------
extern "C" void kernel_launch(void* const* d_in, const int* in_sizes, int n_in,
                              void* d_out, int out_size) {
    const float* x        = (const float*)d_in[0];
    const float* g_w      = (const float*)d_in[1];
    const float* g_b      = (const float*)d_in[2];
    const float* theta_w  = (const float*)d_in[3];
    const float* theta_b  = (const float*)d_in[4];
    const float* phi_w    = (const float*)d_in[5];
    const float* phi_b    = (const float*)d_in[6];
    const float* out_w    = (const float*)d_in[7];
    const float* out_b    = (const float*)d_in[8];
    const float* bn_gamma = (const float*)d_in[9];
    const float* bn_beta  = (const float*)d_in[10];
    float* out = (float*)d_out;

    static bool attr_done = false;
    if (!attr_done) {
        cudaFuncSetAttribute(attn_kernel,
                             cudaFuncAttributeMaxDynamicSharedMemorySize,
                             (int)ATTN_SMEM_BYTES);
        attr_done = true;
    }

    qkv_kernel<<<dim3(128, BB), 128>>>(x, g_w, g_b, theta_w, theta_b,
                                       phi_w, phi_b, out_w);
    attn_kernel<<<dim3(64, BB), 512, ATTN_SMEM_BYTES>>>();
    ynorm_kernel<<<16, 256>>>();
    fuse_kernel<<<512, 512>>>(x, out_b, out);      // 4th launch -> profiled
    reduce_kernel<<<C, 256>>>();
    norm_kernel<<<2048, 256>>>(out, bn_gamma, bn_beta);
}

// round 13
// speedup vs baseline: 1.0252x; 1.0252x over previous
#include <cuda_runtime.h>

#define BB 4
#define C 64
#define IC 16
#define H 128
#define W 128
#define DH 64
#define DW 64
#define NN 4096  // DH*DW

// ---------------- scratch (device globals; no allocation) ----------------
__device__ __align__(16) float g_q[BB*NN*IC];      // tf32(LOG2E*q) bits, [b][n][ic]
__device__ __align__(16) float g_k2[BB*8*NN*2];    // K pair-interleaved tf32 bits: [b][pair][n][2]
__device__ __align__(16) float g_v2[BB*IC*NN];     // V transposed [b][ic][n]
__device__ __align__(16) float g_y[BB*IC*NN];
__device__ __align__(16) float g_yp[2][BB*IC*NN];  // split-KV partial sums
__device__ __align__(16) float g_dp[2][BB*NN];     // split-KV partial denominators
__device__ __align__(16) unsigned long long g_wpk[C*IC];  // out_w packed pairs
__device__ __align__(16) float g_ps[2][C][1024];   // per-warp BN partials
__device__ float g_sum[C];
__device__ float g_sqs[C];

typedef unsigned long long ull;
typedef unsigned int uint;

__device__ __forceinline__ ull pk2(float x, float y) {
    ull r;
    asm("mov.b64 %0, {%1,%2};" : "=l"(r) : "f"(x), "f"(y));
    return r;
}
__device__ __forceinline__ void upk2(ull v, float& lo, float& hi) {
    asm("mov.b64 {%0,%1}, %2;" : "=f"(lo), "=f"(hi) : "l"(v));
}
__device__ __forceinline__ void fma2(ull& d, ull a, ull b) {
    asm("fma.rn.f32x2 %0, %1, %2, %3;" : "=l"(d) : "l"(a), "l"(b), "l"(d));
}
__device__ __forceinline__ ull add2(ull a, ull b) {
    ull r;
    asm("add.rn.f32x2 %0, %1, %2;" : "=l"(r) : "l"(a), "l"(b));
    return r;
}
__device__ __forceinline__ float ex2f(float x) {
    float r;
    asm("ex2.approx.f32 %0, %1;" : "=f"(r) : "f"(x));
    return r;
}
__device__ __forceinline__ uint tf32c(float f) {
    uint r;
    asm("cvt.rna.tf32.f32 %0, %1;" : "=r"(r) : "f"(f));
    return r;
}
__device__ __forceinline__ void mma_tf32(float* c, const uint* a, uint b0, uint b1) {
    asm("mma.sync.aligned.m16n8k8.row.col.f32.tf32.tf32.f32 "
        "{%0,%1,%2,%3}, {%4,%5,%6,%7}, {%8,%9}, {%0,%1,%2,%3};"
        : "+f"(c[0]), "+f"(c[1]), "+f"(c[2]), "+f"(c[3])
        : "r"(a[0]), "r"(a[1]), "r"(a[2]), "r"(a[3]), "r"(b0), "r"(b1));
}
__device__ __forceinline__ void cpa16(uint dst, const void* src) {
    asm volatile("cp.async.ca.shared.global [%0], [%1], 16;" :: "r"(dst), "l"(src));
}

#define LOG2E 1.4426950408889634f

// ---------------- Kernel 1: downsample + Q/K/V projections (+ out_w packing) ----------------
__global__ void qkv_kernel(const float* __restrict__ x,
                           const float* __restrict__ g_w,  const float* __restrict__ g_b,
                           const float* __restrict__ th_w, const float* __restrict__ th_b,
                           const float* __restrict__ ph_w, const float* __restrict__ ph_b,
                           const float* __restrict__ out_w) {
    __shared__ float xd_s[C][32];
    __shared__ float w_s[48][C];
    __shared__ float b_s[48];
    int b = blockIdx.y, tile = blockIdx.x, tid = threadIdx.x;

    if (b == 0 && tile < 4) {
        int base = tile * 256;
        #pragma unroll
        for (int i = 0; i < 2; i++) {
            int idx = base + tid + i * 128;
            float w = out_w[idx];
            g_wpk[idx] = pk2(w, w);
        }
    }

    for (int idx = tid; idx < 48 * C; idx += 128) {
        int o = idx >> 6, c = idx & 63;
        float w;
        if (o < 16)      w = th_w[o * C + c];
        else if (o < 32) w = ph_w[(o - 16) * C + c];
        else             w = g_w[(o - 32) * C + c];
        w_s[o][c] = w;
    }
    if (tid < 48)
        b_s[tid] = (tid < 16) ? th_b[tid] : ((tid < 32) ? ph_b[tid - 16] : g_b[tid - 32]);

    int n0 = tile * 32;
    for (int idx = tid; idx < C * 32; idx += 128) {
        int c = idx >> 5, p = idx & 31;
        int n = n0 + p;
        int i = n >> 6, j = n & 63;
        xd_s[c][p] = x[(((b * C + c) * H + 2 * i + 1) * W) + 2 * j + 1];
    }
    __syncthreads();

    int p = tid & 31, og = tid >> 5;
    int n = n0 + p;
    #pragma unroll
    for (int r = 0; r < 12; r++) {
        int o = og + 4 * r;
        float a0 = b_s[o], a1 = 0.f, a2 = 0.f, a3 = 0.f;
        #pragma unroll
        for (int c = 0; c < C; c += 4) {
            a0 = fmaf(w_s[o][c + 0], xd_s[c + 0][p], a0);
            a1 = fmaf(w_s[o][c + 1], xd_s[c + 1][p], a1);
            a2 = fmaf(w_s[o][c + 2], xd_s[c + 2][p], a2);
            a3 = fmaf(w_s[o][c + 3], xd_s[c + 3][p], a3);
        }
        float acc = (a0 + a1) + (a2 + a3);
        if (o < 16) {
            g_q[(b * NN + n) * IC + o] = __uint_as_float(tf32c(acc * LOG2E));
        } else if (o < 32) {
            // K pair-interleaved: pair p<4 = (ic p, p+4); pair p>=4 = (ic p+4, p+8)
            int ic = o - 16;
            int pr = (ic & 3) + ((ic >= 8) ? 4 : 0);
            int slot = (ic >> 2) & 1;
            g_k2[(((b * 8 + pr) * NN) + n) * 2 + slot] = __uint_as_float(tf32c(acc));
        } else {
            g_v2[(b * IC + (o - 32)) * NN + n] = acc;   // transposed [ic][n]
        }
    }
}

// ---------------- Kernel 2: tensor-core flash attention, split-KV x2, 2-stage ----------------
#define TK 128
#define QQ 128
#define NSPLIT 2
#define KHALF (NN / NSPLIT)
#define NTILES (KHALF / TK)   // 16
#define KROW 264              // ks2 row stride (uints): 256 + 8 pad
#define VROW 136              // vsT row stride (floats): 128 + 8 pad

struct AttnSmem {
    uint  ks2[2][8][KROW];                 // K pairs: [pair][key*2+slot]
    __align__(16) float vsT[2][IC][VROW];  // V transposed [ic][key]
    float redY[2][QQ][17];
    float redD[2][QQ];
};
#define ATTN_SMEM_BYTES sizeof(AttnSmem)

__global__ __launch_bounds__(512) void attn_kernel() {
    extern __shared__ __align__(16) char smem_raw[];
    AttnSmem& sm = *reinterpret_cast<AttnSmem*>(smem_raw);

    int b = blockIdx.y;
    int tile = blockIdx.x >> 1;
    int kv = blockIdx.x & 1;
    int t = threadIdx.x;
    int w = t >> 5, lane = t & 31;
    int qw = w & 7, kh = w >> 3;
    int r = lane >> 2, cc = lane & 3;
    int n0 = tile * QQ;
    int kbase = kv * KHALF;

    uint A0[4], A1[4];
    {
        const uint* qb = (const uint*)(g_q + (b * NN + n0 + qw * 16) * IC);
        A0[0] = qb[ r      * IC + cc     ];
        A0[1] = qb[(r + 8) * IC + cc     ];
        A0[2] = qb[ r      * IC + cc + 4 ];
        A0[3] = qb[(r + 8) * IC + cc + 4 ];
        A1[0] = qb[ r      * IC + cc + 8 ];
        A1[1] = qb[(r + 8) * IC + cc + 8 ];
        A1[2] = qb[ r      * IC + cc + 12];
        A1[3] = qb[(r + 8) * IC + cc + 12];
    }

    float Y0[4] = {0.f, 0.f, 0.f, 0.f};
    float Y1[4] = {0.f, 0.f, 0.f, 0.f};
    float denr = 0.f, dens = 0.f;

    const float* kb = g_k2 + b * 8 * NN * 2;
    const float* vb = g_v2 + b * IC * NN;

    // staging: K = 8 rows x 256 words (512 x 16B chunks); V = 16 rows x 128 words (512 chunks)
    int kp = t >> 6, kc = t & 63;     // K: pair row, 16B chunk within row
    int vi = t >> 5, vc = t & 31;     // V: ic row, 16B chunk

    uint ks_d[2], vs_d[2];
    #pragma unroll
    for (int bf = 0; bf < 2; bf++) {
        ks_d[bf] = (uint)__cvta_generic_to_shared(&sm.ks2[bf][kp][kc * 4]);
        vs_d[bf] = (uint)__cvta_generic_to_shared(&sm.vsT[bf][vi][vc * 4]);
    }

    cpa16(ks_d[0], kb + kp * NN * 2 + kbase * 2 + kc * 4);
    cpa16(vs_d[0], vb + vi * NN + kbase + vc * 4);
    asm volatile("cp.async.commit_group;");

    for (int it = 0; it < NTILES; it++) {
        int cur = it & 1;
        if (it < NTILES - 1) {
            int nxt = cur ^ 1, kt = kbase + (it + 1) * TK;
            cpa16(ks_d[nxt], kb + kp * NN * 2 + kt * 2 + kc * 4);
            cpa16(vs_d[nxt], vb + vi * NN + kt + vc * 4);
            asm volatile("cp.async.commit_group;");
            asm volatile("cp.async.wait_group 1;");
        } else {
            asm volatile("cp.async.wait_group 0;");
        }
        __syncthreads();

        #pragma unroll
        for (int nt = 0; nt < 8; nt++) {
            int key0 = kh * 64 + nt * 8;
            // S-mma B operands: one LDS.64 per k-step (pair-interleaved K)
            uint2 kA0 = *(const uint2*)&sm.ks2[cur][cc    ][(key0 + r) * 2];
            uint2 kA1 = *(const uint2*)&sm.ks2[cur][cc + 4][(key0 + r) * 2];
            float S[4] = {0.f, 0.f, 0.f, 0.f};
            mma_tf32(S, A0, kA0.x, kA0.y);
            mma_tf32(S, A1, kA1.x, kA1.y);

            float e0 = ex2f(S[0]);
            float e1 = ex2f(S[1]);
            float e2 = ex2f(S[2]);
            float e3 = ex2f(S[3]);
            denr += e0 + e1;
            dens += e2 + e3;

            uint P[4];
            P[0] = __float_as_uint(e0);
            P[1] = __float_as_uint(e2);
            P[2] = __float_as_uint(e1);
            P[3] = __float_as_uint(e3);
            int ka = key0 + 2 * cc;
            // PV B operands: adjacent keys in transposed V -> one LDS.64 each
            uint2 v0 = *(const uint2*)&sm.vsT[cur][r    ][ka];
            uint2 v1 = *(const uint2*)&sm.vsT[cur][r + 8][ka];
            mma_tf32(Y0, P, v0.x, v0.y);
            mma_tf32(Y1, P, v1.x, v1.y);
        }
        __syncthreads();
    }

    denr += __shfl_xor_sync(0xffffffffu, denr, 1);
    denr += __shfl_xor_sync(0xffffffffu, denr, 2);
    dens += __shfl_xor_sync(0xffffffffu, dens, 1);
    dens += __shfl_xor_sync(0xffffffffu, dens, 2);

    {
        int q0 = qw * 16 + r, q1 = q0 + 8;
        sm.redY[kh][q0][2 * cc]     = Y0[0];
        sm.redY[kh][q0][2 * cc + 1] = Y0[1];
        sm.redY[kh][q1][2 * cc]     = Y0[2];
        sm.redY[kh][q1][2 * cc + 1] = Y0[3];
        sm.redY[kh][q0][8 + 2 * cc]     = Y1[0];
        sm.redY[kh][q0][8 + 2 * cc + 1] = Y1[1];
        sm.redY[kh][q1][8 + 2 * cc]     = Y1[2];
        sm.redY[kh][q1][8 + 2 * cc + 1] = Y1[3];
        if (cc == 0) {
            sm.redD[kh][q0] = denr;
            sm.redD[kh][q1] = dens;
        }
    }
    __syncthreads();

    {
        int q = t >> 2, ic = (t & 3) * 4;
        #pragma unroll
        for (int j = 0; j < 4; j++) {
            float v = sm.redY[0][q][ic + j] + sm.redY[1][q][ic + j];
            g_yp[kv][(b * IC + ic + j) * NN + n0 + q] = v;
        }
        if ((t & 3) == 0)
            g_dp[kv][b * NN + n0 + q] = sm.redD[0][q] + sm.redD[1][q];
    }
}

// ---------------- Kernel 2b: merge split-KV partials, normalize ----------------
__global__ void ynorm_kernel() {
    int t = blockIdx.x * 256 + threadIdx.x;   // 0..4095
    int b = t >> 10;
    int n4 = (t & 1023) * 4;
    float4 d0 = *(const float4*)&g_dp[0][b * NN + n4];
    float4 d1 = *(const float4*)&g_dp[1][b * NN + n4];
    float4 inv;
    inv.x = 1.f / (d0.x + d1.x);
    inv.y = 1.f / (d0.y + d1.y);
    inv.z = 1.f / (d0.z + d1.z);
    inv.w = 1.f / (d0.w + d1.w);
    #pragma unroll
    for (int ic = 0; ic < IC; ic++) {
        int idx = (b * IC + ic) * NN + n4;
        float4 a = *(const float4*)&g_yp[0][idx];
        float4 c = *(const float4*)&g_yp[1][idx];
        float4 o;
        o.x = (a.x + c.x) * inv.x;
        o.y = (a.y + c.y) * inv.y;
        o.z = (a.z + c.z) * inv.z;
        o.w = (a.w + c.w) * inv.w;
        *(float4*)&g_y[idx] = o;
    }
}

// ---------------- Kernel 3: upsample + out-proj + residual + per-warp BN partials ----------------
// grid 512 (b = bx>>7, row = bx&127), block 512. Full output row per block.
__global__ __launch_bounds__(512) void fuse_kernel(const float* __restrict__ x,
                                                   const float* __restrict__ out_b,
                                                   float* __restrict__ out) {
    __shared__ __align__(8) float yup[IC][128];
    __shared__ ull wsm2[C][IC];
    __shared__ float bsm[C];
    int bx = blockIdx.x;
    int b  = bx >> 7;
    int row = bx & 127;
    int t = threadIdx.x;

    #pragma unroll
    for (int i = 0; i < 2; i++) {
        int idx = t + 512 * i;
        wsm2[idx >> 4][idx & 15] = g_wpk[idx];
    }
    if (t < C) bsm[t] = out_b[t];

    float fi = 0.5f * row - 0.5f;
    int r0 = (int)floorf(fi);
    float wi = fi - (float)r0;
    int r1 = min(r0 + 1, DH - 1);
    r0 = max(r0, 0);

    #pragma unroll
    for (int i = 0; i < 4; i++) {
        int idx = t + 512 * i;          // IC*128 = 2048 elements
        int ic = idx >> 7, p = idx & 127;
        float fj = 0.5f * p - 0.5f;
        int c0 = (int)floorf(fj);
        float wj = fj - (float)c0;
        int c1 = min(c0 + 1, DW - 1);
        c0 = max(c0, 0);
        const float* yp = g_y + (b * IC + ic) * NN;
        float v00 = yp[r0 * DW + c0], v01 = yp[r0 * DW + c1];
        float v10 = yp[r1 * DW + c0], v11 = yp[r1 * DW + c1];
        yup[ic][p] = (1.f - wi) * fmaf(wj, v01 - v00, v00)
                   +        wi  * fmaf(wj, v11 - v10, v10);
    }
    __syncthreads();

    int p2 = t & 63, cg = t >> 6;   // pixel pair 0..63, channel group 0..7 (warp-uniform)
    ull yv[16];
    #pragma unroll
    for (int i2 = 0; i2 < 16; i2++) yv[i2] = *(const ull*)&yup[i2][2 * p2];

    float s1v[8], s2v[8];
    #pragma unroll
    for (int k = 0; k < 8; k++) {
        int c = cg * 8 + k;
        float bb = bsm[c];
        ull acc0 = pk2(bb, bb);
        ull acc1 = 0ull;
        #pragma unroll
        for (int i2 = 0; i2 < 8; i2++)  fma2(acc0, wsm2[c][i2], yv[i2]);
        #pragma unroll
        for (int i2 = 8; i2 < 16; i2++) fma2(acc1, wsm2[c][i2], yv[i2]);
        ull acc = add2(acc0, acc1);
        int gi = ((b * C + c) * H + row) * W + 2 * p2;
        ull xv = *(const ull*)(x + gi);
        acc = add2(acc, xv);
        *(ull*)(out + gi) = acc;
        float lo, hi;
        upk2(acc, lo, hi);
        s1v[k] = lo + hi;
        s2v[k] = fmaf(lo, lo, hi * hi);
    }

    #pragma unroll
    for (int k = 0; k < 8; k++) {
        #pragma unroll
        for (int off = 16; off; off >>= 1) {
            s1v[k] += __shfl_xor_sync(0xffffffffu, s1v[k], off);
            s2v[k] += __shfl_xor_sync(0xffffffffu, s2v[k], off);
        }
    }
    if ((t & 31) == 0) {
        int slot = bx * 2 + ((t >> 5) & 1);   // two warps per channel group
        #pragma unroll
        for (int k = 0; k < 8; k++) {
            g_ps[0][cg * 8 + k][slot] = s1v[k];
            g_ps[1][cg * 8 + k][slot] = s2v[k];
        }
    }
}

// ---------------- Kernel 3b: reduce per-warp partials (no atomics, overwrites) ----------------
__global__ void reduce_kernel() {
    __shared__ float s1s[8], s2s[8];
    int c = blockIdx.x, t = threadIdx.x;
    float s1 = 0.f, s2 = 0.f;
    #pragma unroll
    for (int i = 0; i < 4; i++) {
        s1 += g_ps[0][c][t + 256 * i];
        s2 += g_ps[1][c][t + 256 * i];
    }
    #pragma unroll
    for (int off = 16; off; off >>= 1) {
        s1 += __shfl_xor_sync(0xffffffffu, s1, off);
        s2 += __shfl_xor_sync(0xffffffffu, s2, off);
    }
    int w = t >> 5;
    if ((t & 31) == 0) { s1s[w] = s1; s2s[w] = s2; }
    __syncthreads();
    if (t == 0) {
        float a1 = 0.f, a2 = 0.f;
        #pragma unroll
        for (int i = 0; i < 8; i++) { a1 += s1s[i]; a2 += s2s[i]; }
        g_sum[c] = a1;
        g_sqs[c] = a2;
    }
}

// ---------------- Kernel 4: finalize + apply BN affine in place (8 elems/thread) ----------------
__global__ void norm_kernel(float* __restrict__ out,
                            const float* __restrict__ bn_gamma,
                            const float* __restrict__ bn_beta) {
    int e = (blockIdx.x * 256 + threadIdx.x) * 8;
    int c = (e >> 14) & 63;
    const float npix = (float)(BB * H * W);
    float mean = g_sum[c] / npix;
    float var  = g_sqs[c] / npix - mean * mean;
    float rstd = rsqrtf(var + 1e-5f);
    float a  = bn_gamma[c] * rstd;
    float sh = bn_beta[c] - mean * a;
    float4 v0 = *(float4*)(out + e);
    float4 v1 = *(float4*)(out + e + 4);
    v0.x = fmaf(v0.x, a, sh); v0.y = fmaf(v0.y, a, sh);
    v0.z = fmaf(v0.z, a, sh); v0.w = fmaf(v0.w, a, sh);
    v1.x = fmaf(v1.x, a, sh); v1.y = fmaf(v1.y, a, sh);
    v1.z = fmaf(v1.z, a, sh); v1.w = fmaf(v1.w, a, sh);
    *(float4*)(out + e)     = v0;
    *(float4*)(out + e + 4) = v1;
}

// ---------------- launch ----------------
extern "C" void kernel_launch(void* const* d_in, const int* in_sizes, int n_in,
                              void* d_out, int out_size) {
    const float* x        = (const float*)d_in[0];
    const float* g_w      = (const float*)d_in[1];
    const float* g_b      = (const float*)d_in[2];
    const float* theta_w  = (const float*)d_in[3];
    const float* theta_b  = (const float*)d_in[4];
    const float* phi_w    = (const float*)d_in[5];
    const float* phi_b    = (const float*)d_in[6];
    const float* out_w    = (const float*)d_in[7];
    const float* out_b    = (const float*)d_in[8];
    const float* bn_gamma = (const float*)d_in[9];
    const float* bn_beta  = (const float*)d_in[10];
    float* out = (float*)d_out;

    static bool attr_done = false;
    if (!attr_done) {
        cudaFuncSetAttribute(attn_kernel,
                             cudaFuncAttributeMaxDynamicSharedMemorySize,
                             (int)ATTN_SMEM_BYTES);
        attr_done = true;
    }

    qkv_kernel<<<dim3(128, BB), 128>>>(x, g_w, g_b, theta_w, theta_b,
                                       phi_w, phi_b, out_w);
    attn_kernel<<<dim3(64, BB), 512, ATTN_SMEM_BYTES>>>();
    ynorm_kernel<<<16, 256>>>();
    fuse_kernel<<<512, 512>>>(x, out_b, out);      // 4th launch -> profiled
    reduce_kernel<<<C, 256>>>();
    norm_kernel<<<2048, 256>>>(out, bn_gamma, bn_beta);
}

// round 14
// speedup vs baseline: 1.1051x; 1.0779x over previous
#include <cuda_runtime.h>

#define BB 4
#define C 64
#define IC 16
#define H 128
#define W 128
#define DH 64
#define DW 64
#define NN 4096  // DH*DW

// ---------------- scratch (device globals; no allocation) ----------------
__device__ __align__(16) float g_q[BB*NN*IC];      // tf32(LOG2E*q) bits, [b][n][ic]
__device__ __align__(16) float g_k2[BB*8*NN*2];    // K pair-interleaved tf32 bits
__device__ __align__(16) float g_v2[BB*IC*NN];     // V transposed [b][ic][n]
__device__ __align__(16) float g_y[BB*IC*NN];
__device__ __align__(16) float g_yp[2][BB*IC*NN];  // split-KV partial sums
__device__ __align__(16) float g_dp[2][BB*NN];     // split-KV partial denominators
__device__ __align__(16) unsigned long long g_wpk[C*IC];  // out_w packed pairs
__device__ __align__(16) float g_ps[2][C][1024];   // per-warp BN partials
__device__ float g_sum[C];
__device__ float g_sqs[C];
__device__ unsigned int g_cnt[BB * 32];            // split-k arrival counters (zero-init)

typedef unsigned long long ull;
typedef unsigned int uint;

__device__ __forceinline__ ull pk2(float x, float y) {
    ull r;
    asm("mov.b64 %0, {%1,%2};" : "=l"(r) : "f"(x), "f"(y));
    return r;
}
__device__ __forceinline__ void upk2(ull v, float& lo, float& hi) {
    asm("mov.b64 {%0,%1}, %2;" : "=f"(lo), "=f"(hi) : "l"(v));
}
__device__ __forceinline__ void fma2(ull& d, ull a, ull b) {
    asm("fma.rn.f32x2 %0, %1, %2, %3;" : "=l"(d) : "l"(a), "l"(b), "l"(d));
}
__device__ __forceinline__ ull add2(ull a, ull b) {
    ull r;
    asm("add.rn.f32x2 %0, %1, %2;" : "=l"(r) : "l"(a), "l"(b));
    return r;
}
__device__ __forceinline__ float ex2f(float x) {
    float r;
    asm("ex2.approx.f32 %0, %1;" : "=f"(r) : "f"(x));
    return r;
}
__device__ __forceinline__ uint tf32c(float f) {
    uint r;
    asm("cvt.rna.tf32.f32 %0, %1;" : "=r"(r) : "f"(f));
    return r;
}
__device__ __forceinline__ void mma_tf32(float* c, const uint* a, uint b0, uint b1) {
    asm("mma.sync.aligned.m16n8k8.row.col.f32.tf32.tf32.f32 "
        "{%0,%1,%2,%3}, {%4,%5,%6,%7}, {%8,%9}, {%0,%1,%2,%3};"
        : "+f"(c[0]), "+f"(c[1]), "+f"(c[2]), "+f"(c[3])
        : "r"(a[0]), "r"(a[1]), "r"(a[2]), "r"(a[3]), "r"(b0), "r"(b1));
}
__device__ __forceinline__ void cpa16(uint dst, const void* src) {
    asm volatile("cp.async.ca.shared.global [%0], [%1], 16;" :: "r"(dst), "l"(src));
}

#define LOG2E 1.4426950408889634f

// ---------------- Kernel 1: downsample + Q/K/V projections (+ out_w packing) ----------------
__global__ void qkv_kernel(const float* __restrict__ x,
                           const float* __restrict__ g_w,  const float* __restrict__ g_b,
                           const float* __restrict__ th_w, const float* __restrict__ th_b,
                           const float* __restrict__ ph_w, const float* __restrict__ ph_b,
                           const float* __restrict__ out_w) {
    __shared__ float xd_s[C][32];
    __shared__ float w_s[48][C];
    __shared__ float b_s[48];
    int b = blockIdx.y, tile = blockIdx.x, tid = threadIdx.x;

    if (b == 0 && tile < 4) {
        int base = tile * 256;
        #pragma unroll
        for (int i = 0; i < 2; i++) {
            int idx = base + tid + i * 128;
            float w = out_w[idx];
            g_wpk[idx] = pk2(w, w);
        }
    }

    for (int idx = tid; idx < 48 * C; idx += 128) {
        int o = idx >> 6, c = idx & 63;
        float w;
        if (o < 16)      w = th_w[o * C + c];
        else if (o < 32) w = ph_w[(o - 16) * C + c];
        else             w = g_w[(o - 32) * C + c];
        w_s[o][c] = w;
    }
    if (tid < 48)
        b_s[tid] = (tid < 16) ? th_b[tid] : ((tid < 32) ? ph_b[tid - 16] : g_b[tid - 32]);

    int n0 = tile * 32;
    for (int idx = tid; idx < C * 32; idx += 128) {
        int c = idx >> 5, p = idx & 31;
        int n = n0 + p;
        int i = n >> 6, j = n & 63;
        xd_s[c][p] = x[(((b * C + c) * H + 2 * i + 1) * W) + 2 * j + 1];
    }
    __syncthreads();

    int p = tid & 31, og = tid >> 5;
    int n = n0 + p;
    #pragma unroll
    for (int r = 0; r < 12; r++) {
        int o = og + 4 * r;
        float a0 = b_s[o], a1 = 0.f, a2 = 0.f, a3 = 0.f;
        #pragma unroll
        for (int c = 0; c < C; c += 4) {
            a0 = fmaf(w_s[o][c + 0], xd_s[c + 0][p], a0);
            a1 = fmaf(w_s[o][c + 1], xd_s[c + 1][p], a1);
            a2 = fmaf(w_s[o][c + 2], xd_s[c + 2][p], a2);
            a3 = fmaf(w_s[o][c + 3], xd_s[c + 3][p], a3);
        }
        float acc = (a0 + a1) + (a2 + a3);
        if (o < 16) {
            g_q[(b * NN + n) * IC + o] = __uint_as_float(tf32c(acc * LOG2E));
        } else if (o < 32) {
            int ic = o - 16;
            int pr = (ic & 3) + ((ic >= 8) ? 4 : 0);
            int slot = (ic >> 2) & 1;
            g_k2[(((b * 8 + pr) * NN) + n) * 2 + slot] = __uint_as_float(tf32c(acc));
        } else {
            g_v2[(b * IC + (o - 32)) * NN + n] = acc;
        }
    }
}

// ---------------- Kernel 2: flash attention, split-KV x2, last-CTA merge ----------------
#define TK 128
#define QQ 128
#define NSPLIT 2
#define KHALF (NN / NSPLIT)
#define NTILES (KHALF / TK)   // 16
#define KROW 264
#define VROW 136

struct AttnSmem {
    uint  ks2[2][8][KROW];
    __align__(16) float vsT[2][IC][VROW];
    float redY[2][QQ][17];
    float redD[2][QQ];
    uint flag;
};
#define ATTN_SMEM_BYTES sizeof(AttnSmem)

__global__ __launch_bounds__(512) void attn_kernel() {
    extern __shared__ __align__(16) char smem_raw[];
    AttnSmem& sm = *reinterpret_cast<AttnSmem*>(smem_raw);

    int b = blockIdx.y;
    int tile = blockIdx.x >> 1;
    int kv = blockIdx.x & 1;
    int t = threadIdx.x;
    int w = t >> 5, lane = t & 31;
    int qw = w & 7, kh = w >> 3;
    int r = lane >> 2, cc = lane & 3;
    int n0 = tile * QQ;
    int kbase = kv * KHALF;

    uint A0[4], A1[4];
    {
        const uint* qb = (const uint*)(g_q + (b * NN + n0 + qw * 16) * IC);
        A0[0] = qb[ r      * IC + cc     ];
        A0[1] = qb[(r + 8) * IC + cc     ];
        A0[2] = qb[ r      * IC + cc + 4 ];
        A0[3] = qb[(r + 8) * IC + cc + 4 ];
        A1[0] = qb[ r      * IC + cc + 8 ];
        A1[1] = qb[(r + 8) * IC + cc + 8 ];
        A1[2] = qb[ r      * IC + cc + 12];
        A1[3] = qb[(r + 8) * IC + cc + 12];
    }

    float Y0[4] = {0.f, 0.f, 0.f, 0.f};
    float Y1[4] = {0.f, 0.f, 0.f, 0.f};
    float denr = 0.f, dens = 0.f;

    const float* kb = g_k2 + b * 8 * NN * 2;
    const float* vb = g_v2 + b * IC * NN;

    int kp = t >> 6, kc = t & 63;
    int vi = t >> 5, vc = t & 31;

    uint ks_d[2], vs_d[2];
    #pragma unroll
    for (int bf = 0; bf < 2; bf++) {
        ks_d[bf] = (uint)__cvta_generic_to_shared(&sm.ks2[bf][kp][kc * 4]);
        vs_d[bf] = (uint)__cvta_generic_to_shared(&sm.vsT[bf][vi][vc * 4]);
    }

    cpa16(ks_d[0], kb + kp * NN * 2 + kbase * 2 + kc * 4);
    cpa16(vs_d[0], vb + vi * NN + kbase + vc * 4);
    asm volatile("cp.async.commit_group;");

    for (int it = 0; it < NTILES; it++) {
        int cur = it & 1;
        if (it < NTILES - 1) {
            int nxt = cur ^ 1, kt = kbase + (it + 1) * TK;
            cpa16(ks_d[nxt], kb + kp * NN * 2 + kt * 2 + kc * 4);
            cpa16(vs_d[nxt], vb + vi * NN + kt + vc * 4);
            asm volatile("cp.async.commit_group;");
            asm volatile("cp.async.wait_group 1;");
        } else {
            asm volatile("cp.async.wait_group 0;");
        }
        __syncthreads();

        #pragma unroll
        for (int nt = 0; nt < 8; nt++) {
            int key0 = kh * 64 + nt * 8;
            uint2 kA0 = *(const uint2*)&sm.ks2[cur][cc    ][(key0 + r) * 2];
            uint2 kA1 = *(const uint2*)&sm.ks2[cur][cc + 4][(key0 + r) * 2];
            float S[4] = {0.f, 0.f, 0.f, 0.f};
            mma_tf32(S, A0, kA0.x, kA0.y);
            mma_tf32(S, A1, kA1.x, kA1.y);

            float e0 = ex2f(S[0]);
            float e1 = ex2f(S[1]);
            float e2 = ex2f(S[2]);
            float e3 = ex2f(S[3]);
            denr += e0 + e1;
            dens += e2 + e3;

            uint P[4];
            P[0] = __float_as_uint(e0);
            P[1] = __float_as_uint(e2);
            P[2] = __float_as_uint(e1);
            P[3] = __float_as_uint(e3);
            int ka = key0 + 2 * cc;
            uint2 v0 = *(const uint2*)&sm.vsT[cur][r    ][ka];
            uint2 v1 = *(const uint2*)&sm.vsT[cur][r + 8][ka];
            mma_tf32(Y0, P, v0.x, v0.y);
            mma_tf32(Y1, P, v1.x, v1.y);
        }
        __syncthreads();
    }

    denr += __shfl_xor_sync(0xffffffffu, denr, 1);
    denr += __shfl_xor_sync(0xffffffffu, denr, 2);
    dens += __shfl_xor_sync(0xffffffffu, dens, 1);
    dens += __shfl_xor_sync(0xffffffffu, dens, 2);

    {
        int q0 = qw * 16 + r, q1 = q0 + 8;
        sm.redY[kh][q0][2 * cc]     = Y0[0];
        sm.redY[kh][q0][2 * cc + 1] = Y0[1];
        sm.redY[kh][q1][2 * cc]     = Y0[2];
        sm.redY[kh][q1][2 * cc + 1] = Y0[3];
        sm.redY[kh][q0][8 + 2 * cc]     = Y1[0];
        sm.redY[kh][q0][8 + 2 * cc + 1] = Y1[1];
        sm.redY[kh][q1][8 + 2 * cc]     = Y1[2];
        sm.redY[kh][q1][8 + 2 * cc + 1] = Y1[3];
        if (cc == 0) {
            sm.redD[kh][q0] = denr;
            sm.redD[kh][q1] = dens;
        }
    }
    __syncthreads();

    int q = t >> 2, ic = (t & 3) * 4;
    {
        #pragma unroll
        for (int j = 0; j < 4; j++) {
            float v = sm.redY[0][q][ic + j] + sm.redY[1][q][ic + j];
            g_yp[kv][(b * IC + ic + j) * NN + n0 + q] = v;
        }
        if ((t & 3) == 0)
            g_dp[kv][b * NN + n0 + q] = sm.redD[0][q] + sm.redD[1][q];
    }

    // ---- split-k: last CTA of the (tile) pair merges + normalizes into g_y ----
    __threadfence();
    __syncthreads();
    if (t == 0) sm.flag = atomicAdd(&g_cnt[b * 32 + tile], 1u);
    __syncthreads();
    if (sm.flag == 1u) {
        __threadfence();   // acquire peer partials
        float inv = 1.0f / (g_dp[0][b * NN + n0 + q] + g_dp[1][b * NN + n0 + q]);
        #pragma unroll
        for (int j = 0; j < 4; j++) {
            int idx = (b * IC + ic + j) * NN + n0 + q;
            g_y[idx] = (g_yp[0][idx] + g_yp[1][idx]) * inv;
        }
        if (t == 0) g_cnt[b * 32 + tile] = 0u;   // reset for next graph replay
    }
}

// ---------------- Kernel 3: upsample + out-proj + residual + per-warp BN partials ----------------
// grid 512 (b = bx>>7, row = bx&127), block 512. Full output row per block.
__global__ __launch_bounds__(512) void fuse_kernel(const float* __restrict__ x,
                                                   const float* __restrict__ out_b,
                                                   float* __restrict__ out) {
    __shared__ __align__(8) float yup[IC][128];
    __shared__ ull wsm2[C][IC];
    __shared__ float bsm[C];
    int bx = blockIdx.x;
    int b  = bx >> 7;
    int row = bx & 127;
    int t = threadIdx.x;

    #pragma unroll
    for (int i = 0; i < 2; i++) {
        int idx = t + 512 * i;
        wsm2[idx >> 4][idx & 15] = g_wpk[idx];
    }
    if (t < C) bsm[t] = out_b[t];

    float fi = 0.5f * row - 0.5f;
    int r0 = (int)floorf(fi);
    float wi = fi - (float)r0;
    int r1 = min(r0 + 1, DH - 1);
    r0 = max(r0, 0);

    #pragma unroll
    for (int i = 0; i < 4; i++) {
        int idx = t + 512 * i;
        int ic = idx >> 7, p = idx & 127;
        float fj = 0.5f * p - 0.5f;
        int c0 = (int)floorf(fj);
        float wj = fj - (float)c0;
        int c1 = min(c0 + 1, DW - 1);
        c0 = max(c0, 0);
        const float* yp = g_y + (b * IC + ic) * NN;
        float v00 = yp[r0 * DW + c0], v01 = yp[r0 * DW + c1];
        float v10 = yp[r1 * DW + c0], v11 = yp[r1 * DW + c1];
        yup[ic][p] = (1.f - wi) * fmaf(wj, v01 - v00, v00)
                   +        wi  * fmaf(wj, v11 - v10, v10);
    }
    __syncthreads();

    int p2 = t & 63, cg = t >> 6;
    ull yv[16];
    #pragma unroll
    for (int i2 = 0; i2 < 16; i2++) yv[i2] = *(const ull*)&yup[i2][2 * p2];

    float s1v[8], s2v[8];
    #pragma unroll
    for (int k = 0; k < 8; k++) {
        int c = cg * 8 + k;
        float bb = bsm[c];
        ull acc = pk2(bb, bb);
        #pragma unroll
        for (int i2 = 0; i2 < 16; i2++) fma2(acc, wsm2[c][i2], yv[i2]);
        int gi = ((b * C + c) * H + row) * W + 2 * p2;
        ull xv = *(const ull*)(x + gi);
        acc = add2(acc, xv);
        *(ull*)(out + gi) = acc;
        float lo, hi;
        upk2(acc, lo, hi);
        s1v[k] = lo + hi;
        s2v[k] = fmaf(lo, lo, hi * hi);
    }

    #pragma unroll
    for (int k = 0; k < 8; k++) {
        #pragma unroll
        for (int off = 16; off; off >>= 1) {
            s1v[k] += __shfl_xor_sync(0xffffffffu, s1v[k], off);
            s2v[k] += __shfl_xor_sync(0xffffffffu, s2v[k], off);
        }
    }
    if ((t & 31) == 0) {
        int slot = bx * 2 + ((t >> 5) & 1);
        #pragma unroll
        for (int k = 0; k < 8; k++) {
            g_ps[0][cg * 8 + k][slot] = s1v[k];
            g_ps[1][cg * 8 + k][slot] = s2v[k];
        }
    }
}

// ---------------- Kernel 3b: reduce per-warp partials (no atomics, overwrites) ----------------
__global__ void reduce_kernel() {
    __shared__ float s1s[8], s2s[8];
    int c = blockIdx.x, t = threadIdx.x;
    float s1 = 0.f, s2 = 0.f;
    #pragma unroll
    for (int i = 0; i < 4; i++) {
        s1 += g_ps[0][c][t + 256 * i];
        s2 += g_ps[1][c][t + 256 * i];
    }
    #pragma unroll
    for (int off = 16; off; off >>= 1) {
        s1 += __shfl_xor_sync(0xffffffffu, s1, off);
        s2 += __shfl_xor_sync(0xffffffffu, s2, off);
    }
    int w = t >> 5;
    if ((t & 31) == 0) { s1s[w] = s1; s2s[w] = s2; }
    __syncthreads();
    if (t == 0) {
        float a1 = 0.f, a2 = 0.f;
        #pragma unroll
        for (int i = 0; i < 8; i++) { a1 += s1s[i]; a2 += s2s[i]; }
        g_sum[c] = a1;
        g_sqs[c] = a2;
    }
}

// ---------------- Kernel 4: finalize + apply BN affine in place (8 elems/thread) ----------------
__global__ void norm_kernel(float* __restrict__ out,
                            const float* __restrict__ bn_gamma,
                            const float* __restrict__ bn_beta) {
    int e = (blockIdx.x * 256 + threadIdx.x) * 8;
    int c = (e >> 14) & 63;
    const float npix = (float)(BB * H * W);
    float mean = g_sum[c] / npix;
    float var  = g_sqs[c] / npix - mean * mean;
    float rstd = rsqrtf(var + 1e-5f);
    float a  = bn_gamma[c] * rstd;
    float sh = bn_beta[c] - mean * a;
    float4 v0 = *(float4*)(out + e);
    float4 v1 = *(float4*)(out + e + 4);
    v0.x = fmaf(v0.x, a, sh); v0.y = fmaf(v0.y, a, sh);
    v0.z = fmaf(v0.z, a, sh); v0.w = fmaf(v0.w, a, sh);
    v1.x = fmaf(v1.x, a, sh); v1.y = fmaf(v1.y, a, sh);
    v1.z = fmaf(v1.z, a, sh); v1.w = fmaf(v1.w, a, sh);
    *(float4*)(out + e)     = v0;
    *(float4*)(out + e + 4) = v1;
}

// ---------------- launch ----------------
extern "C" void kernel_launch(void* const* d_in, const int* in_sizes, int n_in,
                              void* d_out, int out_size) {
    const float* x        = (const float*)d_in[0];
    const float* g_w      = (const float*)d_in[1];
    const float* g_b      = (const float*)d_in[2];
    const float* theta_w  = (const float*)d_in[3];
    const float* theta_b  = (const float*)d_in[4];
    const float* phi_w    = (const float*)d_in[5];
    const float* phi_b    = (const float*)d_in[6];
    const float* out_w    = (const float*)d_in[7];
    const float* out_b    = (const float*)d_in[8];
    const float* bn_gamma = (const float*)d_in[9];
    const float* bn_beta  = (const float*)d_in[10];
    float* out = (float*)d_out;

    static bool attr_done = false;
    if (!attr_done) {
        cudaFuncSetAttribute(attn_kernel,
                             cudaFuncAttributeMaxDynamicSharedMemorySize,
                             (int)ATTN_SMEM_BYTES);
        attr_done = true;
    }

    qkv_kernel<<<dim3(128, BB), 128>>>(x, g_w, g_b, theta_w, theta_b,
                                       phi_w, phi_b, out_w);
    attn_kernel<<<dim3(64, BB), 512, ATTN_SMEM_BYTES>>>();
    fuse_kernel<<<512, 512>>>(x, out_b, out);
    reduce_kernel<<<C, 256>>>();
    norm_kernel<<<2048, 256>>>(out, bn_gamma, bn_beta);
}

// round 15
// speedup vs baseline: 1.1379x; 1.0297x over previous
#include <cuda_runtime.h>

#define BB 4
#define C 64
#define IC 16
#define H 128
#define W 128
#define DH 64
#define DW 64
#define NN 4096  // DH*DW

// ---------------- scratch (device globals; no allocation) ----------------
__device__ __align__(16) float g_q[BB*NN*IC];      // tf32(LOG2E*q) bits, [b][n][ic]
__device__ __align__(16) float g_k2[BB*8*NN*2];    // K pair-interleaved tf32 bits
__device__ __align__(16) float g_v2[BB*IC*NN];     // V transposed [b][ic][n]
__device__ __align__(16) float g_y[BB*IC*NN];
__device__ __align__(16) float g_yp[2][BB*IC*NN];  // split-KV partial sums
__device__ __align__(16) float g_dp[2][BB*NN];     // split-KV partial denominators
__device__ __align__(16) unsigned long long g_wpk[C*IC];  // out_w packed pairs
__device__ __align__(16) float g_ps[2][C][1024];   // per-warp BN partials
__device__ unsigned int g_cnt[BB * 32];            // split-k arrival counters (zero-init)

typedef unsigned long long ull;
typedef unsigned int uint;

__device__ __forceinline__ ull pk2(float x, float y) {
    ull r;
    asm("mov.b64 %0, {%1,%2};" : "=l"(r) : "f"(x), "f"(y));
    return r;
}
__device__ __forceinline__ void upk2(ull v, float& lo, float& hi) {
    asm("mov.b64 {%0,%1}, %2;" : "=f"(lo), "=f"(hi) : "l"(v));
}
__device__ __forceinline__ void fma2(ull& d, ull a, ull b) {
    asm("fma.rn.f32x2 %0, %1, %2, %3;" : "=l"(d) : "l"(a), "l"(b), "l"(d));
}
__device__ __forceinline__ ull add2(ull a, ull b) {
    ull r;
    asm("add.rn.f32x2 %0, %1, %2;" : "=l"(r) : "l"(a), "l"(b));
    return r;
}
__device__ __forceinline__ float ex2f(float x) {
    float r;
    asm("ex2.approx.f32 %0, %1;" : "=f"(r) : "f"(x));
    return r;
}
__device__ __forceinline__ uint tf32c(float f) {
    uint r;
    asm("cvt.rna.tf32.f32 %0, %1;" : "=r"(r) : "f"(f));
    return r;
}
__device__ __forceinline__ void mma_tf32(float* c, const uint* a, uint b0, uint b1) {
    asm("mma.sync.aligned.m16n8k8.row.col.f32.tf32.tf32.f32 "
        "{%0,%1,%2,%3}, {%4,%5,%6,%7}, {%8,%9}, {%0,%1,%2,%3};"
        : "+f"(c[0]), "+f"(c[1]), "+f"(c[2]), "+f"(c[3])
        : "r"(a[0]), "r"(a[1]), "r"(a[2]), "r"(a[3]), "r"(b0), "r"(b1));
}
__device__ __forceinline__ void cpa16(uint dst, const void* src) {
    asm volatile("cp.async.ca.shared.global [%0], [%1], 16;" :: "r"(dst), "l"(src));
}

#define LOG2E 1.4426950408889634f

// ---------------- Kernel 1: downsample + Q/K/V projections (+ out_w packing) ----------------
__global__ void qkv_kernel(const float* __restrict__ x,
                           const float* __restrict__ g_w,  const float* __restrict__ g_b,
                           const float* __restrict__ th_w, const float* __restrict__ th_b,
                           const float* __restrict__ ph_w, const float* __restrict__ ph_b,
                           const float* __restrict__ out_w) {
    __shared__ float xd_s[C][32];
    __shared__ float w_s[48][C];
    __shared__ float b_s[48];
    int b = blockIdx.y, tile = blockIdx.x, tid = threadIdx.x;

    if (b == 0 && tile < 4) {
        int base = tile * 256;
        #pragma unroll
        for (int i = 0; i < 2; i++) {
            int idx = base + tid + i * 128;
            float w = out_w[idx];
            g_wpk[idx] = pk2(w, w);
        }
    }

    for (int idx = tid; idx < 48 * C; idx += 128) {
        int o = idx >> 6, c = idx & 63;
        float w;
        if (o < 16)      w = th_w[o * C + c];
        else if (o < 32) w = ph_w[(o - 16) * C + c];
        else             w = g_w[(o - 32) * C + c];
        w_s[o][c] = w;
    }
    if (tid < 48)
        b_s[tid] = (tid < 16) ? th_b[tid] : ((tid < 32) ? ph_b[tid - 16] : g_b[tid - 32]);

    int n0 = tile * 32;
    for (int idx = tid; idx < C * 32; idx += 128) {
        int c = idx >> 5, p = idx & 31;
        int n = n0 + p;
        int i = n >> 6, j = n & 63;
        xd_s[c][p] = x[(((b * C + c) * H + 2 * i + 1) * W) + 2 * j + 1];
    }
    __syncthreads();

    int p = tid & 31, og = tid >> 5;
    int n = n0 + p;
    #pragma unroll
    for (int r = 0; r < 12; r++) {
        int o = og + 4 * r;
        float a0 = b_s[o], a1 = 0.f, a2 = 0.f, a3 = 0.f;
        #pragma unroll
        for (int c = 0; c < C; c += 4) {
            a0 = fmaf(w_s[o][c + 0], xd_s[c + 0][p], a0);
            a1 = fmaf(w_s[o][c + 1], xd_s[c + 1][p], a1);
            a2 = fmaf(w_s[o][c + 2], xd_s[c + 2][p], a2);
            a3 = fmaf(w_s[o][c + 3], xd_s[c + 3][p], a3);
        }
        float acc = (a0 + a1) + (a2 + a3);
        if (o < 16) {
            g_q[(b * NN + n) * IC + o] = __uint_as_float(tf32c(acc * LOG2E));
        } else if (o < 32) {
            int ic = o - 16;
            int pr = (ic & 3) + ((ic >= 8) ? 4 : 0);
            int slot = (ic >> 2) & 1;
            g_k2[(((b * 8 + pr) * NN) + n) * 2 + slot] = __uint_as_float(tf32c(acc));
        } else {
            g_v2[(b * IC + (o - 32)) * NN + n] = acc;
        }
    }
}

// ---------------- Kernel 2: flash attention, split-KV x2, last-CTA merge ----------------
#define TK 128
#define QQ 128
#define NSPLIT 2
#define KHALF (NN / NSPLIT)
#define NTILES (KHALF / TK)   // 16
#define KROW 264
#define VROW 136

struct AttnSmem {
    uint  ks2[2][8][KROW];
    __align__(16) float vsT[2][IC][VROW];
    float redY[2][QQ][17];
    float redD[2][QQ];
    uint flag;
};
#define ATTN_SMEM_BYTES sizeof(AttnSmem)

__global__ __launch_bounds__(512) void attn_kernel() {
    extern __shared__ __align__(16) char smem_raw[];
    AttnSmem& sm = *reinterpret_cast<AttnSmem*>(smem_raw);

    int b = blockIdx.y;
    int tile = blockIdx.x >> 1;
    int kv = blockIdx.x & 1;
    int t = threadIdx.x;
    int w = t >> 5, lane = t & 31;
    int qw = w & 7, kh = w >> 3;
    int r = lane >> 2, cc = lane & 3;
    int n0 = tile * QQ;
    int kbase = kv * KHALF;

    uint A0[4], A1[4];
    {
        const uint* qb = (const uint*)(g_q + (b * NN + n0 + qw * 16) * IC);
        A0[0] = qb[ r      * IC + cc     ];
        A0[1] = qb[(r + 8) * IC + cc     ];
        A0[2] = qb[ r      * IC + cc + 4 ];
        A0[3] = qb[(r + 8) * IC + cc + 4 ];
        A1[0] = qb[ r      * IC + cc + 8 ];
        A1[1] = qb[(r + 8) * IC + cc + 8 ];
        A1[2] = qb[ r      * IC + cc + 12];
        A1[3] = qb[(r + 8) * IC + cc + 12];
    }

    float Y0[4] = {0.f, 0.f, 0.f, 0.f};
    float Y1[4] = {0.f, 0.f, 0.f, 0.f};
    float denr = 0.f, dens = 0.f;

    const float* kb = g_k2 + b * 8 * NN * 2;
    const float* vb = g_v2 + b * IC * NN;

    int kp = t >> 6, kc = t & 63;
    int vi = t >> 5, vc = t & 31;

    uint ks_d[2], vs_d[2];
    #pragma unroll
    for (int bf = 0; bf < 2; bf++) {
        ks_d[bf] = (uint)__cvta_generic_to_shared(&sm.ks2[bf][kp][kc * 4]);
        vs_d[bf] = (uint)__cvta_generic_to_shared(&sm.vsT[bf][vi][vc * 4]);
    }

    cpa16(ks_d[0], kb + kp * NN * 2 + kbase * 2 + kc * 4);
    cpa16(vs_d[0], vb + vi * NN + kbase + vc * 4);
    asm volatile("cp.async.commit_group;");

    for (int it = 0; it < NTILES; it++) {
        int cur = it & 1;
        if (it < NTILES - 1) {
            int nxt = cur ^ 1, kt = kbase + (it + 1) * TK;
            cpa16(ks_d[nxt], kb + kp * NN * 2 + kt * 2 + kc * 4);
            cpa16(vs_d[nxt], vb + vi * NN + kt + vc * 4);
            asm volatile("cp.async.commit_group;");
            asm volatile("cp.async.wait_group 1;");
        } else {
            asm volatile("cp.async.wait_group 0;");
        }
        __syncthreads();

        #pragma unroll
        for (int nt = 0; nt < 8; nt++) {
            int key0 = kh * 64 + nt * 8;
            uint2 kA0 = *(const uint2*)&sm.ks2[cur][cc    ][(key0 + r) * 2];
            uint2 kA1 = *(const uint2*)&sm.ks2[cur][cc + 4][(key0 + r) * 2];
            float S[4] = {0.f, 0.f, 0.f, 0.f};
            mma_tf32(S, A0, kA0.x, kA0.y);
            mma_tf32(S, A1, kA1.x, kA1.y);

            float e0 = ex2f(S[0]);
            float e1 = ex2f(S[1]);
            float e2 = ex2f(S[2]);
            float e3 = ex2f(S[3]);
            denr += e0 + e1;
            dens += e2 + e3;

            uint P[4];
            P[0] = __float_as_uint(e0);
            P[1] = __float_as_uint(e2);
            P[2] = __float_as_uint(e1);
            P[3] = __float_as_uint(e3);
            int ka = key0 + 2 * cc;
            uint2 v0 = *(const uint2*)&sm.vsT[cur][r    ][ka];
            uint2 v1 = *(const uint2*)&sm.vsT[cur][r + 8][ka];
            mma_tf32(Y0, P, v0.x, v0.y);
            mma_tf32(Y1, P, v1.x, v1.y);
        }
        __syncthreads();
    }

    denr += __shfl_xor_sync(0xffffffffu, denr, 1);
    denr += __shfl_xor_sync(0xffffffffu, denr, 2);
    dens += __shfl_xor_sync(0xffffffffu, dens, 1);
    dens += __shfl_xor_sync(0xffffffffu, dens, 2);

    {
        int q0 = qw * 16 + r, q1 = q0 + 8;
        sm.redY[kh][q0][2 * cc]     = Y0[0];
        sm.redY[kh][q0][2 * cc + 1] = Y0[1];
        sm.redY[kh][q1][2 * cc]     = Y0[2];
        sm.redY[kh][q1][2 * cc + 1] = Y0[3];
        sm.redY[kh][q0][8 + 2 * cc]     = Y1[0];
        sm.redY[kh][q0][8 + 2 * cc + 1] = Y1[1];
        sm.redY[kh][q1][8 + 2 * cc]     = Y1[2];
        sm.redY[kh][q1][8 + 2 * cc + 1] = Y1[3];
        if (cc == 0) {
            sm.redD[kh][q0] = denr;
            sm.redD[kh][q1] = dens;
        }
    }
    __syncthreads();

    int q = t >> 2, ic = (t & 3) * 4;
    {
        #pragma unroll
        for (int j = 0; j < 4; j++) {
            float v = sm.redY[0][q][ic + j] + sm.redY[1][q][ic + j];
            g_yp[kv][(b * IC + ic + j) * NN + n0 + q] = v;
        }
        if ((t & 3) == 0)
            g_dp[kv][b * NN + n0 + q] = sm.redD[0][q] + sm.redD[1][q];
    }

    // ---- split-k: last CTA of the (tile) pair merges + normalizes into g_y ----
    __threadfence();
    __syncthreads();
    if (t == 0) sm.flag = atomicAdd(&g_cnt[b * 32 + tile], 1u);
    __syncthreads();
    if (sm.flag == 1u) {
        __threadfence();   // acquire peer partials
        float inv = 1.0f / (g_dp[0][b * NN + n0 + q] + g_dp[1][b * NN + n0 + q]);
        #pragma unroll
        for (int j = 0; j < 4; j++) {
            int idx = (b * IC + ic + j) * NN + n0 + q;
            g_y[idx] = (g_yp[0][idx] + g_yp[1][idx]) * inv;
        }
        if (t == 0) g_cnt[b * 32 + tile] = 0u;   // reset for next graph replay
    }
}

// ---------------- Kernel 3: upsample + out-proj + residual + per-warp BN partials ----------------
// grid 512 (b = bx>>7, row = bx&127), block 512. Full output row per block.
__global__ __launch_bounds__(512) void fuse_kernel(const float* __restrict__ x,
                                                   const float* __restrict__ out_b,
                                                   float* __restrict__ out) {
    __shared__ __align__(8) float yup[IC][128];
    __shared__ ull wsm2[C][IC];
    __shared__ float bsm[C];
    int bx = blockIdx.x;
    int b  = bx >> 7;
    int row = bx & 127;
    int t = threadIdx.x;

    #pragma unroll
    for (int i = 0; i < 2; i++) {
        int idx = t + 512 * i;
        wsm2[idx >> 4][idx & 15] = g_wpk[idx];
    }
    if (t < C) bsm[t] = out_b[t];

    float fi = 0.5f * row - 0.5f;
    int r0 = (int)floorf(fi);
    float wi = fi - (float)r0;
    int r1 = min(r0 + 1, DH - 1);
    r0 = max(r0, 0);

    #pragma unroll
    for (int i = 0; i < 4; i++) {
        int idx = t + 512 * i;
        int ic = idx >> 7, p = idx & 127;
        float fj = 0.5f * p - 0.5f;
        int c0 = (int)floorf(fj);
        float wj = fj - (float)c0;
        int c1 = min(c0 + 1, DW - 1);
        c0 = max(c0, 0);
        const float* yp = g_y + (b * IC + ic) * NN;
        float v00 = yp[r0 * DW + c0], v01 = yp[r0 * DW + c1];
        float v10 = yp[r1 * DW + c0], v11 = yp[r1 * DW + c1];
        yup[ic][p] = (1.f - wi) * fmaf(wj, v01 - v00, v00)
                   +        wi  * fmaf(wj, v11 - v10, v10);
    }
    __syncthreads();

    int p2 = t & 63, cg = t >> 6;
    ull yv[16];
    #pragma unroll
    for (int i2 = 0; i2 < 16; i2++) yv[i2] = *(const ull*)&yup[i2][2 * p2];

    float s1v[8], s2v[8];
    #pragma unroll
    for (int k = 0; k < 8; k++) {
        int c = cg * 8 + k;
        float bb = bsm[c];
        ull acc = pk2(bb, bb);
        #pragma unroll
        for (int i2 = 0; i2 < 16; i2++) fma2(acc, wsm2[c][i2], yv[i2]);
        int gi = ((b * C + c) * H + row) * W + 2 * p2;
        ull xv = *(const ull*)(x + gi);
        acc = add2(acc, xv);
        *(ull*)(out + gi) = acc;
        float lo, hi;
        upk2(acc, lo, hi);
        s1v[k] = lo + hi;
        s2v[k] = fmaf(lo, lo, hi * hi);
    }

    #pragma unroll
    for (int k = 0; k < 8; k++) {
        #pragma unroll
        for (int off = 16; off; off >>= 1) {
            s1v[k] += __shfl_xor_sync(0xffffffffu, s1v[k], off);
            s2v[k] += __shfl_xor_sync(0xffffffffu, s2v[k], off);
        }
    }
    if ((t & 31) == 0) {
        int slot = bx * 2 + ((t >> 5) & 1);
        #pragma unroll
        for (int k = 0; k < 8; k++) {
            g_ps[0][cg * 8 + k][slot] = s1v[k];
            g_ps[1][cg * 8 + k][slot] = s2v[k];
        }
    }
}

// ---------------- Kernel 4: reduce BN partials + apply affine (fused) ----------------
// grid 2048, block 256. Each block covers 2048 contiguous elements = one channel slice.
__global__ void norm_kernel(float* __restrict__ out,
                            const float* __restrict__ bn_gamma,
                            const float* __restrict__ bn_beta) {
    __shared__ float s1s[8], s2s[8];
    __shared__ float ab[2];
    int bid = blockIdx.x, t = threadIdx.x;
    int c = (bid >> 3) & 63;

    // per-block reduction of this channel's 1024 partials (L2-resident)
    float s1 = 0.f, s2 = 0.f;
    #pragma unroll
    for (int i = 0; i < 4; i++) {
        s1 += g_ps[0][c][t + 256 * i];
        s2 += g_ps[1][c][t + 256 * i];
    }
    #pragma unroll
    for (int off = 16; off; off >>= 1) {
        s1 += __shfl_xor_sync(0xffffffffu, s1, off);
        s2 += __shfl_xor_sync(0xffffffffu, s2, off);
    }
    int w = t >> 5;
    if ((t & 31) == 0) { s1s[w] = s1; s2s[w] = s2; }
    __syncthreads();
    if (t == 0) {
        float a1 = 0.f, a2 = 0.f;
        #pragma unroll
        for (int i = 0; i < 8; i++) { a1 += s1s[i]; a2 += s2s[i]; }
        const float npix = (float)(BB * H * W);
        float mean = a1 / npix;
        float var  = a2 / npix - mean * mean;
        float rstd = rsqrtf(var + 1e-5f);
        float a = bn_gamma[c] * rstd;
        ab[0] = a;
        ab[1] = bn_beta[c] - mean * a;
    }
    __syncthreads();
    float a = ab[0], sh = ab[1];

    int e = (bid * 256 + t) * 8;
    float4 v0 = *(float4*)(out + e);
    float4 v1 = *(float4*)(out + e + 4);
    v0.x = fmaf(v0.x, a, sh); v0.y = fmaf(v0.y, a, sh);
    v0.z = fmaf(v0.z, a, sh); v0.w = fmaf(v0.w, a, sh);
    v1.x = fmaf(v1.x, a, sh); v1.y = fmaf(v1.y, a, sh);
    v1.z = fmaf(v1.z, a, sh); v1.w = fmaf(v1.w, a, sh);
    *(float4*)(out + e)     = v0;
    *(float4*)(out + e + 4) = v1;
}

// ---------------- launch ----------------
extern "C" void kernel_launch(void* const* d_in, const int* in_sizes, int n_in,
                              void* d_out, int out_size) {
    const float* x        = (const float*)d_in[0];
    const float* g_w      = (const float*)d_in[1];
    const float* g_b      = (const float*)d_in[2];
    const float* theta_w  = (const float*)d_in[3];
    const float* theta_b  = (const float*)d_in[4];
    const float* phi_w    = (const float*)d_in[5];
    const float* phi_b    = (const float*)d_in[6];
    const float* out_w    = (const float*)d_in[7];
    const float* out_b    = (const float*)d_in[8];
    const float* bn_gamma = (const float*)d_in[9];
    const float* bn_beta  = (const float*)d_in[10];
    float* out = (float*)d_out;

    static bool attr_done = false;
    if (!attr_done) {
        cudaFuncSetAttribute(attn_kernel,
                             cudaFuncAttributeMaxDynamicSharedMemorySize,
                             (int)ATTN_SMEM_BYTES);
        attr_done = true;
    }

    qkv_kernel<<<dim3(128, BB), 128>>>(x, g_w, g_b, theta_w, theta_b,
                                       phi_w, phi_b, out_w);
    attn_kernel<<<dim3(64, BB), 512, ATTN_SMEM_BYTES>>>();
    fuse_kernel<<<512, 512>>>(x, out_b, out);
    norm_kernel<<<2048, 256>>>(out, bn_gamma, bn_beta);
}

// round 16
// speedup vs baseline: 1.1384x; 1.0004x over previous
#include <cuda_runtime.h>

#define BB 4
#define C 64
#define IC 16
#define H 128
#define W 128
#define DH 64
#define DW 64
#define NN 4096  // DH*DW

// ---------------- scratch (device globals; no allocation) ----------------
__device__ __align__(16) float g_q[BB*NN*IC];      // tf32(LOG2E*q) bits, [b][n][ic]
__device__ __align__(16) float g_k2[BB*8*NN*2];    // K pair-interleaved tf32 bits
__device__ __align__(16) float g_v2[BB*IC*NN];     // V transposed [b][ic][n]
__device__ __align__(16) float g_y[BB*IC*NN];
__device__ __align__(16) float g_yp[2][BB*IC*NN];  // split-KV partial sums
__device__ __align__(16) float g_dp[2][BB*NN];     // split-KV partial denominators
__device__ __align__(16) unsigned long long g_wpk[C*IC];  // out_w packed pairs
__device__ __align__(16) float g_ps[2][C][1024];   // per-warp BN partials
__device__ unsigned int g_cnt[BB * 32];            // split-k arrival counters (zero-init)

typedef unsigned long long ull;
typedef unsigned int uint;

__device__ __forceinline__ ull pk2(float x, float y) {
    ull r;
    asm("mov.b64 %0, {%1,%2};" : "=l"(r) : "f"(x), "f"(y));
    return r;
}
__device__ __forceinline__ void upk2(ull v, float& lo, float& hi) {
    asm("mov.b64 {%0,%1}, %2;" : "=f"(lo), "=f"(hi) : "l"(v));
}
__device__ __forceinline__ void fma2(ull& d, ull a, ull b) {
    asm("fma.rn.f32x2 %0, %1, %2, %3;" : "=l"(d) : "l"(a), "l"(b), "l"(d));
}
__device__ __forceinline__ ull add2(ull a, ull b) {
    ull r;
    asm("add.rn.f32x2 %0, %1, %2;" : "=l"(r) : "l"(a), "l"(b));
    return r;
}
__device__ __forceinline__ float ex2f(float x) {
    float r;
    asm("ex2.approx.f32 %0, %1;" : "=f"(r) : "f"(x));
    return r;
}
__device__ __forceinline__ uint tf32c(float f) {
    uint r;
    asm("cvt.rna.tf32.f32 %0, %1;" : "=r"(r) : "f"(f));
    return r;
}
__device__ __forceinline__ void mma_tf32(float* c, const uint* a, uint b0, uint b1) {
    asm("mma.sync.aligned.m16n8k8.row.col.f32.tf32.tf32.f32 "
        "{%0,%1,%2,%3}, {%4,%5,%6,%7}, {%8,%9}, {%0,%1,%2,%3};"
        : "+f"(c[0]), "+f"(c[1]), "+f"(c[2]), "+f"(c[3])
        : "r"(a[0]), "r"(a[1]), "r"(a[2]), "r"(a[3]), "r"(b0), "r"(b1));
}
__device__ __forceinline__ void cpa16(uint dst, const void* src) {
    asm volatile("cp.async.ca.shared.global [%0], [%1], 16;" :: "r"(dst), "l"(src));
}

#define LOG2E 1.4426950408889634f

// ---------------- Kernel 1: downsample + Q/K/V projections (+ out_w packing) ----------------
__global__ void qkv_kernel(const float* __restrict__ x,
                           const float* __restrict__ g_w,  const float* __restrict__ g_b,
                           const float* __restrict__ th_w, const float* __restrict__ th_b,
                           const float* __restrict__ ph_w, const float* __restrict__ ph_b,
                           const float* __restrict__ out_w) {
    __shared__ float xd_s[C][32];
    __shared__ float w_s[48][C];
    __shared__ float b_s[48];
    int b = blockIdx.y, tile = blockIdx.x, tid = threadIdx.x;

    if (b == 0 && tile < 4) {
        int base = tile * 256;
        #pragma unroll
        for (int i = 0; i < 2; i++) {
            int idx = base + tid + i * 128;
            float w = out_w[idx];
            g_wpk[idx] = pk2(w, w);
        }
    }

    for (int idx = tid; idx < 48 * C; idx += 128) {
        int o = idx >> 6, c = idx & 63;
        float w;
        if (o < 16)      w = th_w[o * C + c];
        else if (o < 32) w = ph_w[(o - 16) * C + c];
        else             w = g_w[(o - 32) * C + c];
        w_s[o][c] = w;
    }
    if (tid < 48)
        b_s[tid] = (tid < 16) ? th_b[tid] : ((tid < 32) ? ph_b[tid - 16] : g_b[tid - 32]);

    int n0 = tile * 32;
    for (int idx = tid; idx < C * 32; idx += 128) {
        int c = idx >> 5, p = idx & 31;
        int n = n0 + p;
        int i = n >> 6, j = n & 63;
        xd_s[c][p] = x[(((b * C + c) * H + 2 * i + 1) * W) + 2 * j + 1];
    }
    __syncthreads();

    int p = tid & 31, og = tid >> 5;
    int n = n0 + p;
    #pragma unroll
    for (int r = 0; r < 12; r++) {
        int o = og + 4 * r;
        float a0 = b_s[o], a1 = 0.f, a2 = 0.f, a3 = 0.f;
        #pragma unroll
        for (int c = 0; c < C; c += 4) {
            a0 = fmaf(w_s[o][c + 0], xd_s[c + 0][p], a0);
            a1 = fmaf(w_s[o][c + 1], xd_s[c + 1][p], a1);
            a2 = fmaf(w_s[o][c + 2], xd_s[c + 2][p], a2);
            a3 = fmaf(w_s[o][c + 3], xd_s[c + 3][p], a3);
        }
        float acc = (a0 + a1) + (a2 + a3);
        if (o < 16) {
            g_q[(b * NN + n) * IC + o] = __uint_as_float(tf32c(acc * LOG2E));
        } else if (o < 32) {
            int ic = o - 16;
            int pr = (ic & 3) + ((ic >= 8) ? 4 : 0);
            int slot = (ic >> 2) & 1;
            g_k2[(((b * 8 + pr) * NN) + n) * 2 + slot] = __uint_as_float(tf32c(acc));
        } else {
            g_v2[(b * IC + (o - 32)) * NN + n] = acc;
        }
    }
}

// ---------------- Kernel 2: flash attention, split-KV x2, last-CTA merge ----------------
#define TK 128
#define QQ 128
#define NSPLIT 2
#define KHALF (NN / NSPLIT)
#define NTILES (KHALF / TK)   // 16
#define KROW 264
#define VROW 136

struct AttnSmem {
    uint  ks2[2][8][KROW];
    __align__(16) float vsT[2][IC][VROW];
    float redY[2][QQ][17];
    float redD[2][QQ];
    uint flag;
};
#define ATTN_SMEM_BYTES sizeof(AttnSmem)

__global__ __launch_bounds__(512) void attn_kernel() {
    extern __shared__ __align__(16) char smem_raw[];
    AttnSmem& sm = *reinterpret_cast<AttnSmem*>(smem_raw);

    int b = blockIdx.y;
    int tile = blockIdx.x >> 1;
    int kv = blockIdx.x & 1;
    int t = threadIdx.x;
    int w = t >> 5, lane = t & 31;
    int qw = w & 7, kh = w >> 3;
    int r = lane >> 2, cc = lane & 3;
    int n0 = tile * QQ;
    int kbase = kv * KHALF;

    uint A0[4], A1[4];
    {
        const uint* qb = (const uint*)(g_q + (b * NN + n0 + qw * 16) * IC);
        A0[0] = qb[ r      * IC + cc     ];
        A0[1] = qb[(r + 8) * IC + cc     ];
        A0[2] = qb[ r      * IC + cc + 4 ];
        A0[3] = qb[(r + 8) * IC + cc + 4 ];
        A1[0] = qb[ r      * IC + cc + 8 ];
        A1[1] = qb[(r + 8) * IC + cc + 8 ];
        A1[2] = qb[ r      * IC + cc + 12];
        A1[3] = qb[(r + 8) * IC + cc + 12];
    }

    float Y0[4] = {0.f, 0.f, 0.f, 0.f};
    float Y1[4] = {0.f, 0.f, 0.f, 0.f};
    float denr = 0.f, dens = 0.f;

    const float* kb = g_k2 + b * 8 * NN * 2;
    const float* vb = g_v2 + b * IC * NN;

    int kp = t >> 6, kc = t & 63;
    int vi = t >> 5, vc = t & 31;

    uint ks_d[2], vs_d[2];
    #pragma unroll
    for (int bf = 0; bf < 2; bf++) {
        ks_d[bf] = (uint)__cvta_generic_to_shared(&sm.ks2[bf][kp][kc * 4]);
        vs_d[bf] = (uint)__cvta_generic_to_shared(&sm.vsT[bf][vi][vc * 4]);
    }

    cpa16(ks_d[0], kb + kp * NN * 2 + kbase * 2 + kc * 4);
    cpa16(vs_d[0], vb + vi * NN + kbase + vc * 4);
    asm volatile("cp.async.commit_group;");

    for (int it = 0; it < NTILES; it++) {
        int cur = it & 1;
        if (it < NTILES - 1) {
            int nxt = cur ^ 1, kt = kbase + (it + 1) * TK;
            cpa16(ks_d[nxt], kb + kp * NN * 2 + kt * 2 + kc * 4);
            cpa16(vs_d[nxt], vb + vi * NN + kt + vc * 4);
            asm volatile("cp.async.commit_group;");
            asm volatile("cp.async.wait_group 1;");
        } else {
            asm volatile("cp.async.wait_group 0;");
        }
        __syncthreads();

        #pragma unroll
        for (int nt = 0; nt < 8; nt++) {
            int key0 = kh * 64 + nt * 8;
            uint2 kA0 = *(const uint2*)&sm.ks2[cur][cc    ][(key0 + r) * 2];
            uint2 kA1 = *(const uint2*)&sm.ks2[cur][cc + 4][(key0 + r) * 2];
            float S[4] = {0.f, 0.f, 0.f, 0.f};
            mma_tf32(S, A0, kA0.x, kA0.y);
            mma_tf32(S, A1, kA1.x, kA1.y);

            float e0 = ex2f(S[0]);
            float e1 = ex2f(S[1]);
            float e2 = ex2f(S[2]);
            float e3 = ex2f(S[3]);
            denr += e0 + e1;
            dens += e2 + e3;

            uint P[4];
            P[0] = __float_as_uint(e0);
            P[1] = __float_as_uint(e2);
            P[2] = __float_as_uint(e1);
            P[3] = __float_as_uint(e3);
            int ka = key0 + 2 * cc;
            uint2 v0 = *(const uint2*)&sm.vsT[cur][r    ][ka];
            uint2 v1 = *(const uint2*)&sm.vsT[cur][r + 8][ka];
            mma_tf32(Y0, P, v0.x, v0.y);
            mma_tf32(Y1, P, v1.x, v1.y);
        }
        __syncthreads();
    }

    denr += __shfl_xor_sync(0xffffffffu, denr, 1);
    denr += __shfl_xor_sync(0xffffffffu, denr, 2);
    dens += __shfl_xor_sync(0xffffffffu, dens, 1);
    dens += __shfl_xor_sync(0xffffffffu, dens, 2);

    {
        int q0 = qw * 16 + r, q1 = q0 + 8;
        sm.redY[kh][q0][2 * cc]     = Y0[0];
        sm.redY[kh][q0][2 * cc + 1] = Y0[1];
        sm.redY[kh][q1][2 * cc]     = Y0[2];
        sm.redY[kh][q1][2 * cc + 1] = Y0[3];
        sm.redY[kh][q0][8 + 2 * cc]     = Y1[0];
        sm.redY[kh][q0][8 + 2 * cc + 1] = Y1[1];
        sm.redY[kh][q1][8 + 2 * cc]     = Y1[2];
        sm.redY[kh][q1][8 + 2 * cc + 1] = Y1[3];
        if (cc == 0) {
            sm.redD[kh][q0] = denr;
            sm.redD[kh][q1] = dens;
        }
    }
    __syncthreads();

    int q = t >> 2, ic = (t & 3) * 4;
    {
        #pragma unroll
        for (int j = 0; j < 4; j++) {
            float v = sm.redY[0][q][ic + j] + sm.redY[1][q][ic + j];
            g_yp[kv][(b * IC + ic + j) * NN + n0 + q] = v;
        }
        if ((t & 3) == 0)
            g_dp[kv][b * NN + n0 + q] = sm.redD[0][q] + sm.redD[1][q];
    }

    // ---- split-k: last CTA of the (tile) pair merges + normalizes into g_y ----
    __threadfence();
    __syncthreads();
    if (t == 0) sm.flag = atomicAdd(&g_cnt[b * 32 + tile], 1u);
    __syncthreads();
    if (sm.flag == 1u) {
        __threadfence();   // acquire peer partials
        float inv = 1.0f / (g_dp[0][b * NN + n0 + q] + g_dp[1][b * NN + n0 + q]);
        #pragma unroll
        for (int j = 0; j < 4; j++) {
            int idx = (b * IC + ic + j) * NN + n0 + q;
            g_y[idx] = (g_yp[0][idx] + g_yp[1][idx]) * inv;
        }
        if (t == 0) g_cnt[b * 32 + tile] = 0u;   // reset for next graph replay
    }
}

// ---------------- Kernel 3: upsample + out-proj + residual + per-warp BN partials ----------------
// grid 512 (b = bx>>7, row = bx&127), block 512. Full output row per block.
__global__ __launch_bounds__(512) void fuse_kernel(const float* __restrict__ x,
                                                   const float* __restrict__ out_b,
                                                   float* __restrict__ out) {
    __shared__ __align__(8) float yup[IC][128];
    __shared__ ull wsm2[C][IC];
    __shared__ float bsm[C];
    int bx = blockIdx.x;
    int b  = bx >> 7;
    int row = bx & 127;
    int t = threadIdx.x;

    #pragma unroll
    for (int i = 0; i < 2; i++) {
        int idx = t + 512 * i;
        wsm2[idx >> 4][idx & 15] = g_wpk[idx];
    }
    if (t < C) bsm[t] = out_b[t];

    float fi = 0.5f * row - 0.5f;
    int r0 = (int)floorf(fi);
    float wi = fi - (float)r0;
    int r1 = min(r0 + 1, DH - 1);
    r0 = max(r0, 0);

    #pragma unroll
    for (int i = 0; i < 4; i++) {
        int idx = t + 512 * i;
        int ic = idx >> 7, p = idx & 127;
        float fj = 0.5f * p - 0.5f;
        int c0 = (int)floorf(fj);
        float wj = fj - (float)c0;
        int c1 = min(c0 + 1, DW - 1);
        c0 = max(c0, 0);
        const float* yp = g_y + (b * IC + ic) * NN;
        float v00 = yp[r0 * DW + c0], v01 = yp[r0 * DW + c1];
        float v10 = yp[r1 * DW + c0], v11 = yp[r1 * DW + c1];
        yup[ic][p] = (1.f - wi) * fmaf(wj, v01 - v00, v00)
                   +        wi  * fmaf(wj, v11 - v10, v10);
    }
    __syncthreads();

    int p2 = t & 63, cg = t >> 6;
    ull yv[16];
    #pragma unroll
    for (int i2 = 0; i2 < 16; i2++) yv[i2] = *(const ull*)&yup[i2][2 * p2];

    // prefetch all 8 residual x pairs (MLP=8, hides DRAM latency under fma chains)
    ull xvs[8];
    #pragma unroll
    for (int k = 0; k < 8; k++) {
        int c = cg * 8 + k;
        xvs[k] = *(const ull*)(x + ((b * C + c) * H + row) * W + 2 * p2);
    }

    float s1v[8], s2v[8];
    #pragma unroll
    for (int k = 0; k < 8; k++) {
        int c = cg * 8 + k;
        float bb = bsm[c];
        ull acc = pk2(bb, bb);
        #pragma unroll
        for (int i2 = 0; i2 < 16; i2++) fma2(acc, wsm2[c][i2], yv[i2]);
        acc = add2(acc, xvs[k]);
        *(ull*)(out + ((b * C + c) * H + row) * W + 2 * p2) = acc;
        float lo, hi;
        upk2(acc, lo, hi);
        s1v[k] = lo + hi;
        s2v[k] = fmaf(lo, lo, hi * hi);
    }

    #pragma unroll
    for (int k = 0; k < 8; k++) {
        #pragma unroll
        for (int off = 16; off; off >>= 1) {
            s1v[k] += __shfl_xor_sync(0xffffffffu, s1v[k], off);
            s2v[k] += __shfl_xor_sync(0xffffffffu, s2v[k], off);
        }
    }
    if ((t & 31) == 0) {
        int slot = bx * 2 + ((t >> 5) & 1);
        #pragma unroll
        for (int k = 0; k < 8; k++) {
            g_ps[0][cg * 8 + k][slot] = s1v[k];
            g_ps[1][cg * 8 + k][slot] = s2v[k];
        }
    }
}

// ---------------- Kernel 4: reduce BN partials + apply affine (fused) ----------------
// grid 2048, block 256. Each block covers 2048 contiguous elements = one channel slice.
__global__ void norm_kernel(float* __restrict__ out,
                            const float* __restrict__ bn_gamma,
                            const float* __restrict__ bn_beta) {
    __shared__ float s1s[8], s2s[8];
    __shared__ float ab[2];
    int bid = blockIdx.x, t = threadIdx.x;
    int c = (bid >> 3) & 63;

    // issue streaming loads FIRST — latency overlaps with the reduction below
    int e = (bid * 256 + t) * 8;
    float4 v0 = *(float4*)(out + e);
    float4 v1 = *(float4*)(out + e + 4);

    // per-block reduction of this channel's 1024 partials (L2-resident)
    float s1 = 0.f, s2 = 0.f;
    #pragma unroll
    for (int i = 0; i < 4; i++) {
        s1 += g_ps[0][c][t + 256 * i];
        s2 += g_ps[1][c][t + 256 * i];
    }
    #pragma unroll
    for (int off = 16; off; off >>= 1) {
        s1 += __shfl_xor_sync(0xffffffffu, s1, off);
        s2 += __shfl_xor_sync(0xffffffffu, s2, off);
    }
    int w = t >> 5;
    if ((t & 31) == 0) { s1s[w] = s1; s2s[w] = s2; }
    __syncthreads();
    if (t == 0) {
        float a1 = 0.f, a2 = 0.f;
        #pragma unroll
        for (int i = 0; i < 8; i++) { a1 += s1s[i]; a2 += s2s[i]; }
        const float npix = (float)(BB * H * W);
        float mean = a1 / npix;
        float var  = a2 / npix - mean * mean;
        float rstd = rsqrtf(var + 1e-5f);
        float a = bn_gamma[c] * rstd;
        ab[0] = a;
        ab[1] = bn_beta[c] - mean * a;
    }
    __syncthreads();
    float a = ab[0], sh = ab[1];

    v0.x = fmaf(v0.x, a, sh); v0.y = fmaf(v0.y, a, sh);
    v0.z = fmaf(v0.z, a, sh); v0.w = fmaf(v0.w, a, sh);
    v1.x = fmaf(v1.x, a, sh); v1.y = fmaf(v1.y, a, sh);
    v1.z = fmaf(v1.z, a, sh); v1.w = fmaf(v1.w, a, sh);
    *(float4*)(out + e)     = v0;
    *(float4*)(out + e + 4) = v1;
}

// ---------------- launch ----------------
extern "C" void kernel_launch(void* const* d_in, const int* in_sizes, int n_in,
                              void* d_out, int out_size) {
    const float* x        = (const float*)d_in[0];
    const float* g_w      = (const float*)d_in[1];
    const float* g_b      = (const float*)d_in[2];
    const float* theta_w  = (const float*)d_in[3];
    const float* theta_b  = (const float*)d_in[4];
    const float* phi_w    = (const float*)d_in[5];
    const float* phi_b    = (const float*)d_in[6];
    const float* out_w    = (const float*)d_in[7];
    const float* out_b    = (const float*)d_in[8];
    const float* bn_gamma = (const float*)d_in[9];
    const float* bn_beta  = (const float*)d_in[10];
    float* out = (float*)d_out;

    static bool attr_done = false;
    if (!attr_done) {
        cudaFuncSetAttribute(attn_kernel,
                             cudaFuncAttributeMaxDynamicSharedMemorySize,
                             (int)ATTN_SMEM_BYTES);
        attr_done = true;
    }

    qkv_kernel<<<dim3(128, BB), 128>>>(x, g_w, g_b, theta_w, theta_b,
                                       phi_w, phi_b, out_w);
    attn_kernel<<<dim3(64, BB), 512, ATTN_SMEM_BYTES>>>();
    fuse_kernel<<<512, 512>>>(x, out_b, out);
    norm_kernel<<<2048, 256>>>(out, bn_gamma, bn_beta);
}

// round 17
// speedup vs baseline: 1.1453x; 1.0061x over previous
#include <cuda_runtime.h>

#define BB 4
#define C 64
#define IC 16
#define H 128
#define W 128
#define DH 64
#define DW 64
#define NN 4096  // DH*DW

// ---------------- scratch (device globals; no allocation) ----------------
__device__ __align__(16) float g_q[BB*NN*IC];      // tf32(LOG2E*q) bits, [b][n][ic]
__device__ __align__(16) float g_k2[BB*8*NN*2];    // K pair-interleaved tf32 bits
__device__ __align__(16) float g_v2[BB*IC*NN];     // V transposed [b][ic][n]
__device__ __align__(16) float g_y[BB*IC*NN];
__device__ __align__(16) float g_yp[2][BB*IC*NN];  // split-KV partial sums
__device__ __align__(16) float g_dp[2][BB*NN];     // split-KV partial denominators
__device__ __align__(16) unsigned long long g_wpk[C*IC];  // out_w packed pairs
__device__ __align__(16) float g_ps[2][C][1024];   // per-warp BN partials
__device__ unsigned int g_cnt[BB * 32];            // split-k arrival counters (zero-init)

typedef unsigned long long ull;
typedef unsigned int uint;

__device__ __forceinline__ ull pk2(float x, float y) {
    ull r;
    asm("mov.b64 %0, {%1,%2};" : "=l"(r) : "f"(x), "f"(y));
    return r;
}
__device__ __forceinline__ void upk2(ull v, float& lo, float& hi) {
    asm("mov.b64 {%0,%1}, %2;" : "=f"(lo), "=f"(hi) : "l"(v));
}
__device__ __forceinline__ void fma2(ull& d, ull a, ull b) {
    asm("fma.rn.f32x2 %0, %1, %2, %3;" : "=l"(d) : "l"(a), "l"(b), "l"(d));
}
__device__ __forceinline__ ull add2(ull a, ull b) {
    ull r;
    asm("add.rn.f32x2 %0, %1, %2;" : "=l"(r) : "l"(a), "l"(b));
    return r;
}
__device__ __forceinline__ float ex2f(float x) {
    float r;
    asm("ex2.approx.f32 %0, %1;" : "=f"(r) : "f"(x));
    return r;
}
__device__ __forceinline__ uint tf32c(float f) {
    uint r;
    asm("cvt.rna.tf32.f32 %0, %1;" : "=r"(r) : "f"(f));
    return r;
}
__device__ __forceinline__ void mma_tf32(float* c, const uint* a, uint b0, uint b1) {
    asm("mma.sync.aligned.m16n8k8.row.col.f32.tf32.tf32.f32 "
        "{%0,%1,%2,%3}, {%4,%5,%6,%7}, {%8,%9}, {%0,%1,%2,%3};"
        : "+f"(c[0]), "+f"(c[1]), "+f"(c[2]), "+f"(c[3])
        : "r"(a[0]), "r"(a[1]), "r"(a[2]), "r"(a[3]), "r"(b0), "r"(b1));
}
__device__ __forceinline__ void cpa16(uint dst, const void* src) {
    asm volatile("cp.async.ca.shared.global [%0], [%1], 16;" :: "r"(dst), "l"(src));
}

#define LOG2E 1.4426950408889634f

// ---------------- Kernel 1: downsample + Q/K/V projections (+ out_w packing) ----------------
__global__ void qkv_kernel(const float* __restrict__ x,
                           const float* __restrict__ g_w,  const float* __restrict__ g_b,
                           const float* __restrict__ th_w, const float* __restrict__ th_b,
                           const float* __restrict__ ph_w, const float* __restrict__ ph_b,
                           const float* __restrict__ out_w) {
    __shared__ float xd_s[C][32];
    __shared__ float w_s[48][C];
    __shared__ float b_s[48];
    int b = blockIdx.y, tile = blockIdx.x, tid = threadIdx.x;

    if (b == 0 && tile < 4) {
        int base = tile * 256;
        #pragma unroll
        for (int i = 0; i < 2; i++) {
            int idx = base + tid + i * 128;
            float w = out_w[idx];
            g_wpk[idx] = pk2(w, w);
        }
    }

    for (int idx = tid; idx < 48 * C; idx += 128) {
        int o = idx >> 6, c = idx & 63;
        float w;
        if (o < 16)      w = th_w[o * C + c];
        else if (o < 32) w = ph_w[(o - 16) * C + c];
        else             w = g_w[(o - 32) * C + c];
        w_s[o][c] = w;
    }
    if (tid < 48)
        b_s[tid] = (tid < 16) ? th_b[tid] : ((tid < 32) ? ph_b[tid - 16] : g_b[tid - 32]);

    int n0 = tile * 32;
    for (int idx = tid; idx < C * 32; idx += 128) {
        int c = idx >> 5, p = idx & 31;
        int n = n0 + p;
        int i = n >> 6, j = n & 63;
        xd_s[c][p] = x[(((b * C + c) * H + 2 * i + 1) * W) + 2 * j + 1];
    }
    __syncthreads();

    int p = tid & 31, og = tid >> 5;
    int n = n0 + p;
    #pragma unroll
    for (int r = 0; r < 12; r++) {
        int o = og + 4 * r;
        float a0 = b_s[o], a1 = 0.f, a2 = 0.f, a3 = 0.f;
        #pragma unroll
        for (int c = 0; c < C; c += 4) {
            a0 = fmaf(w_s[o][c + 0], xd_s[c + 0][p], a0);
            a1 = fmaf(w_s[o][c + 1], xd_s[c + 1][p], a1);
            a2 = fmaf(w_s[o][c + 2], xd_s[c + 2][p], a2);
            a3 = fmaf(w_s[o][c + 3], xd_s[c + 3][p], a3);
        }
        float acc = (a0 + a1) + (a2 + a3);
        if (o < 16) {
            g_q[(b * NN + n) * IC + o] = __uint_as_float(tf32c(acc * LOG2E));
        } else if (o < 32) {
            int ic = o - 16;
            int pr = (ic & 3) + ((ic >= 8) ? 4 : 0);
            int slot = (ic >> 2) & 1;
            g_k2[(((b * 8 + pr) * NN) + n) * 2 + slot] = __uint_as_float(tf32c(acc));
        } else {
            g_v2[(b * IC + (o - 32)) * NN + n] = acc;
        }
    }
}

// ---------------- Kernel 2: flash attention, split-KV x2, last-CTA merge ----------------
#define TK 128
#define QQ 128
#define NSPLIT 2
#define KHALF (NN / NSPLIT)
#define NTILES (KHALF / TK)   // 16
#define KROW 264
#define VROW 136

struct AttnSmem {
    uint  ks2[2][8][KROW];
    __align__(16) float vsT[2][IC][VROW];
    float redY[2][QQ][17];
    float redD[2][QQ];
    uint flag;
};
#define ATTN_SMEM_BYTES sizeof(AttnSmem)

__global__ __launch_bounds__(512) void attn_kernel() {
    extern __shared__ __align__(16) char smem_raw[];
    AttnSmem& sm = *reinterpret_cast<AttnSmem*>(smem_raw);

    int b = blockIdx.y;
    int tile = blockIdx.x >> 1;
    int kv = blockIdx.x & 1;
    int t = threadIdx.x;
    int w = t >> 5, lane = t & 31;
    int qw = w & 7, kh = w >> 3;
    int r = lane >> 2, cc = lane & 3;
    int n0 = tile * QQ;
    int kbase = kv * KHALF;

    uint A0[4], A1[4];
    {
        const uint* qb = (const uint*)(g_q + (b * NN + n0 + qw * 16) * IC);
        A0[0] = qb[ r      * IC + cc     ];
        A0[1] = qb[(r + 8) * IC + cc     ];
        A0[2] = qb[ r      * IC + cc + 4 ];
        A0[3] = qb[(r + 8) * IC + cc + 4 ];
        A1[0] = qb[ r      * IC + cc + 8 ];
        A1[1] = qb[(r + 8) * IC + cc + 8 ];
        A1[2] = qb[ r      * IC + cc + 12];
        A1[3] = qb[(r + 8) * IC + cc + 12];
    }

    float Y0[4] = {0.f, 0.f, 0.f, 0.f};
    float Y1[4] = {0.f, 0.f, 0.f, 0.f};
    float denr = 0.f, dens = 0.f;

    const float* kb = g_k2 + b * 8 * NN * 2;
    const float* vb = g_v2 + b * IC * NN;

    int kp = t >> 6, kc = t & 63;
    int vi = t >> 5, vc = t & 31;

    uint ks_d[2], vs_d[2];
    #pragma unroll
    for (int bf = 0; bf < 2; bf++) {
        ks_d[bf] = (uint)__cvta_generic_to_shared(&sm.ks2[bf][kp][kc * 4]);
        vs_d[bf] = (uint)__cvta_generic_to_shared(&sm.vsT[bf][vi][vc * 4]);
    }

    cpa16(ks_d[0], kb + kp * NN * 2 + kbase * 2 + kc * 4);
    cpa16(vs_d[0], vb + vi * NN + kbase + vc * 4);
    asm volatile("cp.async.commit_group;");

    for (int it = 0; it < NTILES; it++) {
        int cur = it & 1;
        if (it < NTILES - 1) {
            int nxt = cur ^ 1, kt = kbase + (it + 1) * TK;
            cpa16(ks_d[nxt], kb + kp * NN * 2 + kt * 2 + kc * 4);
            cpa16(vs_d[nxt], vb + vi * NN + kt + vc * 4);
            asm volatile("cp.async.commit_group;");
            asm volatile("cp.async.wait_group 1;");
        } else {
            asm volatile("cp.async.wait_group 0;");
        }
        __syncthreads();

        // batched nt-pairs: issue 4 independent S-mmas, then 8 ex2, then 4 PV-mmas
        #pragma unroll
        for (int nt2 = 0; nt2 < 4; nt2++) {
            int keyA = kh * 64 + nt2 * 16;
            int keyB = keyA + 8;
            uint2 kA0a = *(const uint2*)&sm.ks2[cur][cc    ][(keyA + r) * 2];
            uint2 kA1a = *(const uint2*)&sm.ks2[cur][cc + 4][(keyA + r) * 2];
            uint2 kA0b = *(const uint2*)&sm.ks2[cur][cc    ][(keyB + r) * 2];
            uint2 kA1b = *(const uint2*)&sm.ks2[cur][cc + 4][(keyB + r) * 2];
            float Sa[4] = {0.f, 0.f, 0.f, 0.f};
            float Sb[4] = {0.f, 0.f, 0.f, 0.f};
            mma_tf32(Sa, A0, kA0a.x, kA0a.y);
            mma_tf32(Sb, A0, kA0b.x, kA0b.y);
            mma_tf32(Sa, A1, kA1a.x, kA1a.y);
            mma_tf32(Sb, A1, kA1b.x, kA1b.y);

            float ea0 = ex2f(Sa[0]);
            float ea1 = ex2f(Sa[1]);
            float ea2 = ex2f(Sa[2]);
            float ea3 = ex2f(Sa[3]);
            float eb0 = ex2f(Sb[0]);
            float eb1 = ex2f(Sb[1]);
            float eb2 = ex2f(Sb[2]);
            float eb3 = ex2f(Sb[3]);
            denr += (ea0 + ea1) + (eb0 + eb1);
            dens += (ea2 + ea3) + (eb2 + eb3);

            uint Pa[4], Pb[4];
            Pa[0] = __float_as_uint(ea0);
            Pa[1] = __float_as_uint(ea2);
            Pa[2] = __float_as_uint(ea1);
            Pa[3] = __float_as_uint(ea3);
            Pb[0] = __float_as_uint(eb0);
            Pb[1] = __float_as_uint(eb2);
            Pb[2] = __float_as_uint(eb1);
            Pb[3] = __float_as_uint(eb3);
            int kaA = keyA + 2 * cc;
            int kaB = keyB + 2 * cc;
            uint2 v0a = *(const uint2*)&sm.vsT[cur][r    ][kaA];
            uint2 v1a = *(const uint2*)&sm.vsT[cur][r + 8][kaA];
            uint2 v0b = *(const uint2*)&sm.vsT[cur][r    ][kaB];
            uint2 v1b = *(const uint2*)&sm.vsT[cur][r + 8][kaB];
            mma_tf32(Y0, Pa, v0a.x, v0a.y);
            mma_tf32(Y1, Pa, v1a.x, v1a.y);
            mma_tf32(Y0, Pb, v0b.x, v0b.y);
            mma_tf32(Y1, Pb, v1b.x, v1b.y);
        }
        __syncthreads();
    }

    denr += __shfl_xor_sync(0xffffffffu, denr, 1);
    denr += __shfl_xor_sync(0xffffffffu, denr, 2);
    dens += __shfl_xor_sync(0xffffffffu, dens, 1);
    dens += __shfl_xor_sync(0xffffffffu, dens, 2);

    {
        int q0 = qw * 16 + r, q1 = q0 + 8;
        sm.redY[kh][q0][2 * cc]     = Y0[0];
        sm.redY[kh][q0][2 * cc + 1] = Y0[1];
        sm.redY[kh][q1][2 * cc]     = Y0[2];
        sm.redY[kh][q1][2 * cc + 1] = Y0[3];
        sm.redY[kh][q0][8 + 2 * cc]     = Y1[0];
        sm.redY[kh][q0][8 + 2 * cc + 1] = Y1[1];
        sm.redY[kh][q1][8 + 2 * cc]     = Y1[2];
        sm.redY[kh][q1][8 + 2 * cc + 1] = Y1[3];
        if (cc == 0) {
            sm.redD[kh][q0] = denr;
            sm.redD[kh][q1] = dens;
        }
    }
    __syncthreads();

    int q = t >> 2, ic = (t & 3) * 4;
    {
        #pragma unroll
        for (int j = 0; j < 4; j++) {
            float v = sm.redY[0][q][ic + j] + sm.redY[1][q][ic + j];
            g_yp[kv][(b * IC + ic + j) * NN + n0 + q] = v;
        }
        if ((t & 3) == 0)
            g_dp[kv][b * NN + n0 + q] = sm.redD[0][q] + sm.redD[1][q];
    }

    // ---- split-k: last CTA of the (tile) pair merges + normalizes into g_y ----
    __threadfence();
    __syncthreads();
    if (t == 0) sm.flag = atomicAdd(&g_cnt[b * 32 + tile], 1u);
    __syncthreads();
    if (sm.flag == 1u) {
        __threadfence();   // acquire peer partials
        float inv = 1.0f / (g_dp[0][b * NN + n0 + q] + g_dp[1][b * NN + n0 + q]);
        #pragma unroll
        for (int j = 0; j < 4; j++) {
            int idx = (b * IC + ic + j) * NN + n0 + q;
            g_y[idx] = (g_yp[0][idx] + g_yp[1][idx]) * inv;
        }
        if (t == 0) g_cnt[b * 32 + tile] = 0u;   // reset for next graph replay
    }
}

// ---------------- Kernel 3: upsample + out-proj + residual + per-warp BN partials ----------------
// grid 512 (b = bx>>7, row = bx&127), block 512. Full output row per block.
__global__ __launch_bounds__(512) void fuse_kernel(const float* __restrict__ x,
                                                   const float* __restrict__ out_b,
                                                   float* __restrict__ out) {
    __shared__ __align__(8) float yup[IC][128];
    __shared__ ull wsm2[C][IC];
    __shared__ float bsm[C];
    int bx = blockIdx.x;
    int b  = bx >> 7;
    int row = bx & 127;
    int t = threadIdx.x;

    #pragma unroll
    for (int i = 0; i < 2; i++) {
        int idx = t + 512 * i;
        wsm2[idx >> 4][idx & 15] = g_wpk[idx];
    }
    if (t < C) bsm[t] = out_b[t];

    float fi = 0.5f * row - 0.5f;
    int r0 = (int)floorf(fi);
    float wi = fi - (float)r0;
    int r1 = min(r0 + 1, DH - 1);
    r0 = max(r0, 0);

    #pragma unroll
    for (int i = 0; i < 4; i++) {
        int idx = t + 512 * i;
        int ic = idx >> 7, p = idx & 127;
        float fj = 0.5f * p - 0.5f;
        int c0 = (int)floorf(fj);
        float wj = fj - (float)c0;
        int c1 = min(c0 + 1, DW - 1);
        c0 = max(c0, 0);
        const float* yp = g_y + (b * IC + ic) * NN;
        float v00 = yp[r0 * DW + c0], v01 = yp[r0 * DW + c1];
        float v10 = yp[r1 * DW + c0], v11 = yp[r1 * DW + c1];
        yup[ic][p] = (1.f - wi) * fmaf(wj, v01 - v00, v00)
                   +        wi  * fmaf(wj, v11 - v10, v10);
    }
    __syncthreads();

    int p2 = t & 63, cg = t >> 6;
    ull yv[16];
    #pragma unroll
    for (int i2 = 0; i2 < 16; i2++) yv[i2] = *(const ull*)&yup[i2][2 * p2];

    // prefetch all 8 residual x pairs (MLP=8)
    ull xvs[8];
    #pragma unroll
    for (int k = 0; k < 8; k++) {
        int c = cg * 8 + k;
        xvs[k] = *(const ull*)(x + ((b * C + c) * H + row) * W + 2 * p2);
    }

    float s1v[8], s2v[8];
    #pragma unroll
    for (int k = 0; k < 8; k++) {
        int c = cg * 8 + k;
        float bb = bsm[c];
        ull acc = pk2(bb, bb);
        #pragma unroll
        for (int i2 = 0; i2 < 16; i2++) fma2(acc, wsm2[c][i2], yv[i2]);
        acc = add2(acc, xvs[k]);
        *(ull*)(out + ((b * C + c) * H + row) * W + 2 * p2) = acc;
        float lo, hi;
        upk2(acc, lo, hi);
        s1v[k] = lo + hi;
        s2v[k] = fmaf(lo, lo, hi * hi);
    }

    #pragma unroll
    for (int k = 0; k < 8; k++) {
        #pragma unroll
        for (int off = 16; off; off >>= 1) {
            s1v[k] += __shfl_xor_sync(0xffffffffu, s1v[k], off);
            s2v[k] += __shfl_xor_sync(0xffffffffu, s2v[k], off);
        }
    }
    if ((t & 31) == 0) {
        int slot = bx * 2 + ((t >> 5) & 1);
        #pragma unroll
        for (int k = 0; k < 8; k++) {
            g_ps[0][cg * 8 + k][slot] = s1v[k];
            g_ps[1][cg * 8 + k][slot] = s2v[k];
        }
    }
}

// ---------------- Kernel 4: reduce BN partials + apply affine (fused) ----------------
__global__ void norm_kernel(float* __restrict__ out,
                            const float* __restrict__ bn_gamma,
                            const float* __restrict__ bn_beta) {
    __shared__ float s1s[8], s2s[8];
    __shared__ float ab[2];
    int bid = blockIdx.x, t = threadIdx.x;
    int c = (bid >> 3) & 63;

    int e = (bid * 256 + t) * 8;
    float4 v0 = *(float4*)(out + e);
    float4 v1 = *(float4*)(out + e + 4);

    float s1 = 0.f, s2 = 0.f;
    #pragma unroll
    for (int i = 0; i < 4; i++) {
        s1 += g_ps[0][c][t + 256 * i];
        s2 += g_ps[1][c][t + 256 * i];
    }
    #pragma unroll
    for (int off = 16; off; off >>= 1) {
        s1 += __shfl_xor_sync(0xffffffffu, s1, off);
        s2 += __shfl_xor_sync(0xffffffffu, s2, off);
    }
    int w = t >> 5;
    if ((t & 31) == 0) { s1s[w] = s1; s2s[w] = s2; }
    __syncthreads();
    if (t == 0) {
        float a1 = 0.f, a2 = 0.f;
        #pragma unroll
        for (int i = 0; i < 8; i++) { a1 += s1s[i]; a2 += s2s[i]; }
        const float npix = (float)(BB * H * W);
        float mean = a1 / npix;
        float var  = a2 / npix - mean * mean;
        float rstd = rsqrtf(var + 1e-5f);
        float a = bn_gamma[c] * rstd;
        ab[0] = a;
        ab[1] = bn_beta[c] - mean * a;
    }
    __syncthreads();
    float a = ab[0], sh = ab[1];

    v0.x = fmaf(v0.x, a, sh); v0.y = fmaf(v0.y, a, sh);
    v0.z = fmaf(v0.z, a, sh); v0.w = fmaf(v0.w, a, sh);
    v1.x = fmaf(v1.x, a, sh); v1.y = fmaf(v1.y, a, sh);
    v1.z = fmaf(v1.z, a, sh); v1.w = fmaf(v1.w, a, sh);
    *(float4*)(out + e)     = v0;
    *(float4*)(out + e + 4) = v1;
}

// ---------------- launch ----------------
extern "C" void kernel_launch(void* const* d_in, const int* in_sizes, int n_in,
                              void* d_out, int out_size) {
    const float* x        = (const float*)d_in[0];
    const float* g_w      = (const float*)d_in[1];
    const float* g_b      = (const float*)d_in[2];
    const float* theta_w  = (const float*)d_in[3];
    const float* theta_b  = (const float*)d_in[4];
    const float* phi_w    = (const float*)d_in[5];
    const float* phi_b    = (const float*)d_in[6];
    const float* out_w    = (const float*)d_in[7];
    const float* out_b    = (const float*)d_in[8];
    const float* bn_gamma = (const float*)d_in[9];
    const float* bn_beta  = (const float*)d_in[10];
    float* out = (float*)d_out;

    static bool attr_done = false;
    if (!attr_done) {
        cudaFuncSetAttribute(attn_kernel,
                             cudaFuncAttributeMaxDynamicSharedMemorySize,
                             (int)ATTN_SMEM_BYTES);
        attr_done = true;
    }

    qkv_kernel<<<dim3(128, BB), 128>>>(x, g_w, g_b, theta_w, theta_b,
                                       phi_w, phi_b, out_w);
    attn_kernel<<<dim3(64, BB), 512, ATTN_SMEM_BYTES>>>();
    fuse_kernel<<<512, 512>>>(x, out_b, out);
    norm_kernel<<<2048, 256>>>(out, bn_gamma, bn_beta);
}